// round 10
// baseline (speedup 1.0000x reference)
#include <cuda_runtime.h>
#include <math.h>
#include <stdint.h>

// Problem constants
#define BQ 2
#define CQ 128
#define TQ 32
#define NQ 512
#define PQ (TQ * NQ)      // 16384 points per batch
#define KQ 16
#define HIDQ 512
#define OUTC 132
#define THREEN 1536

// ---------------------------------------------------------------------------
// Device scratch (static — no allocations allowed)
// ---------------------------------------------------------------------------
__device__ float g_xpm[BQ * PQ * CQ];      // x transposed to (b,p,c), full precision (residual)
__device__ float g_xtf[BQ * PQ * CQ];      // x transposed, tf32-rounded (QKV GEMM input)
__device__ float g_qkv[BQ * PQ * 384];     // (b, p, [q(128) | kx(128) | vx(128)])
__device__ int   g_idx[BQ * PQ * KQ];      // neighbor composite index t_eff*N + n'
__device__ float g_h[BQ * PQ * CQ];        // post-attn+BN h, tf32-rounded (W1 input)
__device__ float g_hid[BQ * PQ * HIDQ];    // leaky(W1@h), tf32-rounded (W2 input)
__device__ float g_wq[CQ * CQ], g_wk[CQ * CQ], g_wv[CQ * CQ];   // rounded weights
__device__ float g_w1[HIDQ * CQ], g_w2[CQ * HIDQ];

// ---------------------------------------------------------------------------
// tf32 / async helpers
// ---------------------------------------------------------------------------
__device__ __forceinline__ uint32_t f2tf(float f)
{
    uint32_t r;
    asm("cvt.rna.tf32.f32 %0, %1;" : "=r"(r) : "f"(f));
    return r;
}
__device__ __forceinline__ float f2tff(float f) { return __uint_as_float(f2tf(f)); }

__device__ __forceinline__ void mma_tf32(float c[4],
                                         uint32_t a0, uint32_t a1, uint32_t a2, uint32_t a3,
                                         uint32_t b0, uint32_t b1)
{
    asm volatile(
        "mma.sync.aligned.m16n8k8.row.col.f32.tf32.tf32.f32 "
        "{%0,%1,%2,%3},{%4,%5,%6,%7},{%8,%9},{%0,%1,%2,%3};"
        : "+f"(c[0]), "+f"(c[1]), "+f"(c[2]), "+f"(c[3])
        : "r"(a0), "r"(a1), "r"(a2), "r"(a3), "r"(b0), "r"(b1));
}

__device__ __forceinline__ void cp16(uint32_t* dst_smem, const float* src)
{
    uint32_t d = (uint32_t)__cvta_generic_to_shared(dst_smem);
    asm volatile("cp.async.cg.shared.global [%0], [%1], 16;" :: "r"(d), "l"(src));
}
__device__ __forceinline__ void cp_commit() { asm volatile("cp.async.commit_group;" ::: "memory"); }
template<int N>
__device__ __forceinline__ void cp_wait() { asm volatile("cp.async.wait_group %0;" :: "n"(N) : "memory"); }

// ---------------------------------------------------------------------------
// K_pre: round all weights to tf32 once.
// ---------------------------------------------------------------------------
__global__ void k_roundw(const float* __restrict__ Wq, const float* __restrict__ Wk,
                         const float* __restrict__ Wv, const float* __restrict__ W1,
                         const float* __restrict__ W2)
{
    int i = blockIdx.x * 256 + threadIdx.x;   // 0 .. 65535
    if (i < CQ * CQ) {
        g_wq[i] = f2tff(Wq[i]);
        g_wk[i] = f2tff(Wk[i]);
        g_wv[i] = f2tff(Wv[i]);
    }
    g_w1[i] = f2tff(W1[i]);
    g_w2[i] = f2tff(W2[i]);
}

// ---------------------------------------------------------------------------
// K0: transpose x (B,C,P) -> g_xpm (full) and g_xtf (tf32-rounded), (B,P,C).
// Also writes out channels 0..3 directly.
// ---------------------------------------------------------------------------
__global__ void k_transpose(const float* __restrict__ x, float* __restrict__ out)
{
    __shared__ float tile[32][33];
    int b = blockIdx.z;
    int p0 = blockIdx.x * 32;
    int c0 = blockIdx.y * 32;
    const float* xb = x + (size_t)b * CQ * PQ;
    int tx = threadIdx.x, ty = threadIdx.y;
#pragma unroll
    for (int i = 0; i < 32; i += 8) {
        float v = xb[(size_t)(c0 + ty + i) * PQ + p0 + tx];
        tile[ty + i][tx] = v;
        if (c0 == 0 && (ty + i) < 4)
            out[(size_t)b * OUTC * PQ + (size_t)(ty + i) * PQ + p0 + tx] = v;
    }
    __syncthreads();
    float* op  = g_xpm + (size_t)b * PQ * CQ;
    float* op2 = g_xtf + (size_t)b * PQ * CQ;
#pragma unroll
    for (int i = 0; i < 32; i += 8) {
        float v = tile[tx][ty + i];
        size_t o = (size_t)(p0 + ty + i) * CQ + c0 + tx;
        op[o]  = v;
        op2[o] = f2tff(v);
    }
}

// ---------------------------------------------------------------------------
// K1: top-K neighbor selection (round-8 exact algorithm, full batch grid).
// ---------------------------------------------------------------------------
__global__ void __launch_bounds__(256) k_topk(const float* __restrict__ x)
{
    int t = blockIdx.x, b = blockIdx.y, z = blockIdx.z;
    __shared__ float sc[3][THREEN];
    const float* xb = x + (size_t)b * CQ * PQ;
    int tid = threadIdx.x;

    for (int i = tid; i < 3 * THREEN; i += 256) {
        int c = i / THREEN, m = i % THREEN;
        int j = m >> 9, nn = m & 511;
        int te = t - 1 + j;
        te = te < 0 ? 0 : (te > TQ - 1 ? TQ - 1 : te);
        sc[c][m] = xb[(size_t)c * PQ + te * NQ + nn];
    }
    __syncthreads();

    const unsigned FULL = 0xffffffffu;
    const float FINF = __int_as_float(0x7f800000);
    int lane = tid & 31, w = tid >> 5;

    for (int i = 0; i < 8; i++) {
        int n = z * 64 + w * 8 + i;
        float a0 = sc[0][512 + n], a1 = sc[1][512 + n], a2 = sc[2][512 + n];

        float e0 = FINF, e1 = FINF, e2 = FINF, e3 = FINF;
        int   q0 = 0,    q1 = 0,    q2 = 0,    q3 = 0;
#pragma unroll
        for (int jj = 0; jj < 48; jj++) {
            int m = jj * 32 + lane;
            float dx = sc[0][m] - a0;
            float dy = sc[1][m] - a1;
            float dz = sc[2][m] - a2;
            float dc = dx * dx + dy * dy + dz * dz;
            bool l0 = dc < e0, l1 = dc < e1, l2 = dc < e2, l3 = dc < e3;
            e3 = l3 ? (l2 ? e2 : dc) : e3;  q3 = l3 ? (l2 ? q2 : m) : q3;
            e2 = l2 ? (l1 ? e1 : dc) : e2;  q2 = l2 ? (l1 ? q1 : m) : q2;
            e1 = l1 ? (l0 ? e0 : dc) : e1;  q1 = l1 ? (l0 ? q0 : m) : q1;
            e0 = l0 ? dc : e0;              q0 = l0 ? m : q0;
        }

        int ptr = 0;
        bool bad = false;
        int* orow = g_idx + ((size_t)(b * TQ + t) * NQ + n) * KQ;
#pragma unroll
        for (int it = 0; it < KQ; it++) {
            bad |= __any_sync(FULL, ptr >= 4);
            unsigned long long mykey =
                ((unsigned long long)__float_as_uint(e0) << 32) | (unsigned)q0;
            unsigned long long k = mykey;
#pragma unroll
            for (int off = 16; off; off >>= 1) {
                unsigned long long o = __shfl_xor_sync(FULL, k, off);
                if (o < k) k = o;
            }
            if (mykey == k) {
                e0 = e1; q0 = q1; e1 = e2; q1 = q2; e2 = e3; q2 = q3;
                e3 = FINF; q3 = 0; ptr++;
            }
            if (lane == 0) {
                int m = (int)(k & 0xffffffffu);
                int jwin = m >> 9, nwin = m & 511;
                int te = t - 1 + jwin;
                te = te < 0 ? 0 : (te > TQ - 1 ? TQ - 1 : te);
                orow[it] = te * NQ + nwin;
            }
        }

        if (bad) {
            unsigned long long removed = 0ull;
            for (int it = 0; it < KQ; it++) {
                float best = 3.4e38f;
                int bj = 0;
#pragma unroll
                for (int jj = 0; jj < 48; jj++) {
                    int m = jj * 32 + lane;
                    float dx = sc[0][m] - a0;
                    float dy = sc[1][m] - a1;
                    float dz = sc[2][m] - a2;
                    float dc = dx * dx + dy * dy + dz * dz;
                    bool alive = !(removed & (1ull << jj));
                    if (alive && dc < best) { best = dc; bj = jj; }
                }
                int bm = bj * 32 + lane;
#pragma unroll
                for (int off = 16; off; off >>= 1) {
                    float od = __shfl_xor_sync(FULL, best, off);
                    int   om = __shfl_xor_sync(FULL, bm, off);
                    if (od < best || (od == best && om < bm)) { best = od; bm = om; }
                }
                if ((bm & 31) == lane) removed |= (1ull << (bm >> 5));
                if (lane == 0) {
                    int jwin = bm >> 9, nwin = bm & 511;
                    int te = t - 1 + jwin;
                    te = te < 0 ? 0 : (te > TQ - 1 ? TQ - 1 : te);
                    orow[it] = te * NQ + nwin;
                }
            }
        }
    }
}

// ---------------------------------------------------------------------------
// Streaming tf32 GEMM core (used by W2).
// ---------------------------------------------------------------------------
template<int CIN>
__device__ __forceinline__ void gemm_core(const float* __restrict__ A,
                                          const float* __restrict__ W,
                                          float acc[4][4][4], int tid)
{
    constexpr int KC = 16;
    constexpr int NCH = CIN / KC;
    __shared__ uint32_t As[2][128 * 20];
    __shared__ uint32_t Bs[2][128 * 20];

    const int lane = tid & 31, wid = tid >> 5;
    const int gid = lane >> 2, tig = lane & 3;
    const int mbase = (wid & 1) * 64, nbase = (wid >> 1) * 32;

    const int r0 = tid >> 2, s0 = (tid & 3) * 4;
    const int r1 = r0 + 64;

    {
        cp16(&As[0][r0 * 20 + s0], A + (size_t)r0 * CIN + s0);
        cp16(&As[0][r1 * 20 + s0], A + (size_t)r1 * CIN + s0);
        cp16(&Bs[0][r0 * 20 + s0], W + (size_t)r0 * CIN + s0);
        cp16(&Bs[0][r1 * 20 + s0], W + (size_t)r1 * CIN + s0);
        cp_commit();
    }

#pragma unroll 1
    for (int kc = 0; kc < NCH; kc++) {
        const int st = kc & 1;
        cp_wait<0>();
        __syncthreads();
        if (kc + 1 < NCH) {
            const int k0g = (kc + 1) * KC;
            cp16(&As[st ^ 1][r0 * 20 + s0], A + (size_t)r0 * CIN + k0g + s0);
            cp16(&As[st ^ 1][r1 * 20 + s0], A + (size_t)r1 * CIN + k0g + s0);
            cp16(&Bs[st ^ 1][r0 * 20 + s0], W + (size_t)r0 * CIN + k0g + s0);
            cp16(&Bs[st ^ 1][r1 * 20 + s0], W + (size_t)r1 * CIN + k0g + s0);
            cp_commit();
        }

#pragma unroll
        for (int ks = 0; ks < 2; ks++) {
            const int k0 = ks * 8;
            uint32_t af[4][4], bf[4][2];
#pragma unroll
            for (int mt = 0; mt < 4; mt++) {
                int m = mbase + mt * 16 + gid;
                af[mt][0] = As[st][m * 20 + k0 + tig];
                af[mt][1] = As[st][(m + 8) * 20 + k0 + tig];
                af[mt][2] = As[st][m * 20 + k0 + 4 + tig];
                af[mt][3] = As[st][(m + 8) * 20 + k0 + 4 + tig];
            }
#pragma unroll
            for (int nt = 0; nt < 4; nt++) {
                int n = nbase + nt * 8 + gid;
                bf[nt][0] = Bs[st][n * 20 + k0 + tig];
                bf[nt][1] = Bs[st][n * 20 + k0 + 4 + tig];
            }
#pragma unroll
            for (int mt = 0; mt < 4; mt++)
#pragma unroll
                for (int nt = 0; nt < 4; nt++)
                    mma_tf32(acc[mt][nt], af[mt][0], af[mt][1], af[mt][2], af[mt][3],
                             bf[nt][0], bf[nt][1]);
        }
    }
    __syncthreads();
}

// ---------------------------------------------------------------------------
// A-resident GEMM compute (unchanged).
// ---------------------------------------------------------------------------
__device__ __forceinline__ void gemm_Ares_pass(const uint32_t* __restrict__ As,
                                               uint32_t* __restrict__ Bs,
                                               const float* __restrict__ W,
                                               float acc[4][4][4],
                                               int tid)
{
    const int lane = tid & 31, wid = tid >> 5;
    const int gid = lane >> 2, tig = lane & 3;
    const int mbase = (wid & 1) * 64, nbase = (wid >> 1) * 32;
    const int r0 = tid >> 2, s0 = (tid & 3) * 4;
    const int r1 = r0 + 64;

    cp16(&Bs[r0 * 20 + s0], W + (size_t)r0 * CQ + s0);
    cp16(&Bs[r1 * 20 + s0], W + (size_t)r1 * CQ + s0);
    cp_commit();

#pragma unroll 1
    for (int kc = 0; kc < 8; kc++) {
        const int st = kc & 1;
        cp_wait<0>();
        __syncthreads();
        if (kc + 1 < 8) {
            const int k0g = (kc + 1) * 16;
            uint32_t* Bd = Bs + (st ^ 1) * (128 * 20);
            cp16(&Bd[r0 * 20 + s0], W + (size_t)r0 * CQ + k0g + s0);
            cp16(&Bd[r1 * 20 + s0], W + (size_t)r1 * CQ + k0g + s0);
            cp_commit();
        }
        const uint32_t* Bc = Bs + st * (128 * 20);

#pragma unroll
        for (int ks = 0; ks < 2; ks++) {
            const int ka = kc * 16 + ks * 8;
            const int kb = ks * 8;
            uint32_t af[4][4], bf[4][2];
#pragma unroll
            for (int mt = 0; mt < 4; mt++) {
                int m = mbase + mt * 16 + gid;
                af[mt][0] = As[m * 132 + ka + tig];
                af[mt][1] = As[(m + 8) * 132 + ka + tig];
                af[mt][2] = As[m * 132 + ka + 4 + tig];
                af[mt][3] = As[(m + 8) * 132 + ka + 4 + tig];
            }
#pragma unroll
            for (int nt = 0; nt < 4; nt++) {
                int n = nbase + nt * 8 + gid;
                bf[nt][0] = Bc[n * 20 + kb + tig];
                bf[nt][1] = Bc[n * 20 + kb + 4 + tig];
            }
#pragma unroll
            for (int mt = 0; mt < 4; mt++)
#pragma unroll
                for (int nt = 0; nt < 4; nt++)
                    mma_tf32(acc[mt][nt], af[mt][0], af[mt][1], af[mt][2], af[mt][3],
                             bf[nt][0], bf[nt][1]);
        }
    }
}

#define ARES_SMEM ((128 * 132 + 2 * 128 * 20) * 4)   // 88064 B

// K2: merged QKV projection. grid (PQ/128, B).
__global__ void __launch_bounds__(256) k_gemm_qkv()
{
    extern __shared__ uint32_t sm[];
    uint32_t* As = sm;                    // [128][132]
    uint32_t* Bs = sm + 128 * 132;        // [2][128][20]

    const int b = blockIdx.y;
    const int p0 = blockIdx.x * 128;
    const int tid = threadIdx.x;
    const float* A = g_xtf + (size_t)(b * PQ + p0) * CQ;

#pragma unroll
    for (int it = 0; it < 16; it++) {
        int id = tid + it * 256;
        int r = id >> 5, seg = (id & 31) * 4;
        cp16(&As[r * 132 + seg], A + (size_t)r * CQ + seg);
    }
    cp_commit();

    const int lane = tid & 31, wid = tid >> 5;
    const int gid = lane >> 2, tig = lane & 3;

#pragma unroll 1
    for (int cq = 0; cq < 3; cq++) {
        const float* W = (cq == 0) ? g_wq : ((cq == 1) ? g_wk : g_wv);
        float acc[4][4][4] = {};
        gemm_Ares_pass(As, Bs, W, acc, tid);

        float* base = g_qkv + (size_t)(b * PQ + p0 + (wid & 1) * 64) * 384
                    + cq * 128 + (wid >> 1) * 32;
#pragma unroll
        for (int mt = 0; mt < 4; mt++) {
            int r = mt * 16 + gid;
#pragma unroll
            for (int nt = 0; nt < 4; nt++) {
                int c = nt * 8 + tig * 2;
                *(float2*)(base + (size_t)r * 384 + c)       = make_float2(acc[mt][nt][0], acc[mt][nt][1]);
                *(float2*)(base + (size_t)(r + 8) * 384 + c) = make_float2(acc[mt][nt][2], acc[mt][nt][3]);
            }
        }
    }
}

// K4: W1 with resident h tile, over a half of the points. grid (PQ/256, B).
__global__ void __launch_bounds__(256) k_gemm_w1(int half)
{
    extern __shared__ uint32_t sm[];
    uint32_t* As = sm;
    uint32_t* Bs = sm + 128 * 132;

    const int b = blockIdx.y;
    const int p0 = half * (PQ / 2) + blockIdx.x * 128;
    const int tid = threadIdx.x;
    const float* A = g_h + (size_t)(b * PQ + p0) * CQ;

#pragma unroll
    for (int it = 0; it < 16; it++) {
        int id = tid + it * 256;
        int r = id >> 5, seg = (id & 31) * 4;
        cp16(&As[r * 132 + seg], A + (size_t)r * CQ + seg);
    }
    cp_commit();

    const int lane = tid & 31, wid = tid >> 5;
    const int gid = lane >> 2, tig = lane & 3;

#pragma unroll 1
    for (int nt4 = 0; nt4 < 4; nt4++) {
        const int co0 = nt4 * 128;
        float acc[4][4][4] = {};
        gemm_Ares_pass(As, Bs, g_w1 + (size_t)co0 * CQ, acc, tid);

        float* base = g_hid + (size_t)(b * PQ + p0 + (wid & 1) * 64) * HIDQ
                    + co0 + (wid >> 1) * 32;
#pragma unroll
        for (int mt = 0; mt < 4; mt++) {
            int r = mt * 16 + gid;
#pragma unroll
            for (int nt = 0; nt < 4; nt++) {
                int c = nt * 8 + tig * 2;
                float v0 = acc[mt][nt][0], v1 = acc[mt][nt][1];
                float v2 = acc[mt][nt][2], v3 = acc[mt][nt][3];
                v0 = f2tff(v0 > 0.f ? v0 : 0.2f * v0);
                v1 = f2tff(v1 > 0.f ? v1 : 0.2f * v1);
                v2 = f2tff(v2 > 0.f ? v2 : 0.2f * v2);
                v3 = f2tff(v3 > 0.f ? v3 : 0.2f * v3);
                *(float2*)(base + (size_t)r * HIDQ + c)       = make_float2(v0, v1);
                *(float2*)(base + (size_t)(r + 8) * HIDQ + c) = make_float2(v2, v3);
            }
        }
    }
}

// ---------------------------------------------------------------------------
// K3: attention + residual + BN (full batch, __expf).
// ---------------------------------------------------------------------------
__global__ void __launch_bounds__(256) k_attn(const float* __restrict__ gamma,
                                              const float* __restrict__ beta,
                                              const float* __restrict__ mean,
                                              const float* __restrict__ var)
{
    __shared__ float s_scale[CQ], s_shift[CQ];
    int tid = threadIdx.x;
    if (tid < CQ) {
        float sc = gamma[tid] * rsqrtf(var[tid] + 1e-5f);
        s_scale[tid] = sc;
        s_shift[tid] = beta[tid] - mean[tid] * sc;
    }
    __syncthreads();

    int lane = tid & 31, w = tid >> 5;
    const float rs = 0.17677669529663687f; // 1/sqrt(32)

    for (int i = 0; i < 8; i++) {
        int g = blockIdx.x * 64 + w * 8 + i;
        int b = g >> 14;
        int bbase = b << 14;

        const float4* qk = (const float4*)(g_qkv + (size_t)g * 384);
        float4 qv = qk[lane];
        float4 ks = qk[32 + lane];
        float4 vs = qk[64 + lane];

        const int* irow = g_idx + (size_t)g * KQ;
        int myidx = irow[lane & 15];

        float dself;
        {
            float p = qv.x * ks.x + qv.y * ks.y + qv.z * ks.z + qv.w * ks.w;
            p += __shfl_xor_sync(0xffffffffu, p, 1);
            p += __shfl_xor_sync(0xffffffffu, p, 2);
            p += __shfl_xor_sync(0xffffffffu, p, 4);
            dself = p;
        }

        float e[16];
#pragma unroll
        for (int k = 0; k < 16; k++) {
            int nb = __shfl_sync(0xffffffffu, myidx, k);
            const float4* kp = (const float4*)(g_qkv + (size_t)(bbase + nb) * 384 + 128);
            float4 kn = kp[lane];
            float p = qv.x * kn.x + qv.y * kn.y + qv.z * kn.z + qv.w * kn.w;
            p += __shfl_xor_sync(0xffffffffu, p, 1);
            p += __shfl_xor_sync(0xffffffffu, p, 2);
            p += __shfl_xor_sync(0xffffffffu, p, 4);
            e[k] = (dself - p) * rs;
        }

        float mx = e[0];
#pragma unroll
        for (int k = 1; k < 16; k++) mx = fmaxf(mx, e[k]);
        float s = 0.f;
#pragma unroll
        for (int k = 0; k < 16; k++) { e[k] = __expf(e[k] - mx); s += e[k]; }
        float inv = 1.0f / s;

        float4 acc = vs;
#pragma unroll
        for (int k = 0; k < 16; k++) {
            int nb = __shfl_sync(0xffffffffu, myidx, k);
            const float4* vp = (const float4*)(g_qkv + (size_t)(bbase + nb) * 384 + 256);
            float4 vn = vp[lane];
            float a = e[k] * inv;
            acc.x -= a * vn.x; acc.y -= a * vn.y;
            acc.z -= a * vn.z; acc.w -= a * vn.w;
        }

        const float4* xp = (const float4*)(g_xpm + (size_t)g * CQ);
        float4 xv = xp[lane];
        int c = lane * 4;
        float4 hv;
        hv.x = f2tff((xv.x + acc.x) * s_scale[c + 0] + s_shift[c + 0]);
        hv.y = f2tff((xv.y + acc.y) * s_scale[c + 1] + s_shift[c + 1]);
        hv.z = f2tff((xv.z + acc.z) * s_scale[c + 2] + s_shift[c + 2]);
        hv.w = f2tff((xv.w + acc.w) * s_scale[c + 3] + s_shift[c + 3]);
        ((float4*)(g_h + (size_t)g * CQ))[lane] = hv;
    }
}

// K5: W2 over a half of the points. grid (PQ/256, 1, B).
__global__ void __launch_bounds__(256) k_gemm_w2(float* __restrict__ out, int half)
{
    int b = blockIdx.z;
    int p0 = half * (PQ / 2) + blockIdx.x * 128;

    float acc[4][4][4] = {};
    gemm_core<HIDQ>(g_hid + (size_t)(b * PQ + p0) * HIDQ, g_w2, acc, threadIdx.x);

    const int lane = threadIdx.x & 31, wid = threadIdx.x >> 5;
    const int gid = lane >> 2, tig = lane & 3;
    float* ob = out + (size_t)b * OUTC * PQ + (size_t)4 * PQ;
    int rbase = p0 + (wid & 1) * 64;
    int cbase = (wid >> 1) * 32;
#pragma unroll
    for (int mt = 0; mt < 4; mt++) {
        int r = rbase + mt * 16 + gid;
#pragma unroll
        for (int nt = 0; nt < 4; nt++) {
            int c = cbase + nt * 8 + tig * 2;
            ob[(size_t)c * PQ + r]           = acc[mt][nt][0];
            ob[(size_t)(c + 1) * PQ + r]     = acc[mt][nt][1];
            ob[(size_t)c * PQ + r + 8]       = acc[mt][nt][2];
            ob[(size_t)(c + 1) * PQ + r + 8] = acc[mt][nt][3];
        }
    }
}

// ---------------------------------------------------------------------------
extern "C" void kernel_launch(void* const* d_in, const int* in_sizes, int n_in,
                              void* d_out, int out_size)
{
    const float* x     = (const float*)d_in[0];
    const float* Wq    = (const float*)d_in[1];
    const float* Wk    = (const float*)d_in[2];
    const float* Wv    = (const float*)d_in[3];
    const float* W1    = (const float*)d_in[4];
    const float* W2    = (const float*)d_in[5];
    const float* gamma = (const float*)d_in[6];
    const float* beta  = (const float*)d_in[7];
    const float* mean  = (const float*)d_in[8];
    const float* var   = (const float*)d_in[9];
    float* out = (float*)d_out;

    static cudaStream_t s2, s3;
    static cudaEvent_t evFork, evTk, evW1h0, evW2h0;
    static int init_done = 0;
    if (!init_done) {
        cudaFuncSetAttribute(k_gemm_qkv, cudaFuncAttributeMaxDynamicSharedMemorySize, ARES_SMEM);
        cudaFuncSetAttribute(k_gemm_w1,  cudaFuncAttributeMaxDynamicSharedMemorySize, ARES_SMEM);
        cudaStreamCreateWithFlags(&s2, cudaStreamNonBlocking);
        cudaStreamCreateWithFlags(&s3, cudaStreamNonBlocking);
        cudaEventCreateWithFlags(&evFork,  cudaEventDisableTiming);
        cudaEventCreateWithFlags(&evTk,    cudaEventDisableTiming);
        cudaEventCreateWithFlags(&evW1h0,  cudaEventDisableTiming);
        cudaEventCreateWithFlags(&evW2h0,  cudaEventDisableTiming);
        init_done = 1;
    }

    // Fork: topk depends only on x — run concurrent with roundw/transpose/qkv.
    cudaEventRecord(evFork, 0);
    cudaStreamWaitEvent(s2, evFork, 0);
    k_topk<<<dim3(TQ, BQ, 8), 256, 0, s2>>>(x);
    cudaEventRecord(evTk, s2);

    k_roundw<<<256, 256>>>(Wq, Wk, Wv, W1, W2);
    k_transpose<<<dim3(PQ / 32, CQ / 32, BQ), dim3(32, 8)>>>(x, out);
    k_gemm_qkv<<<dim3(PQ / 128, BQ), 256, ARES_SMEM>>>();

    cudaStreamWaitEvent(0, evTk, 0);
    k_attn<<<dim3((BQ * PQ) / 64, 1, 1), 256>>>(gamma, beta, mean, var);

    // W1/W2 software pipeline by point-halves:
    //   w1(h0) -> [s3: w2(h0)] || w1(h1) -> w2(h1)
    k_gemm_w1<<<dim3(PQ / 256, BQ), 256, ARES_SMEM>>>(0);
    cudaEventRecord(evW1h0, 0);
    cudaStreamWaitEvent(s3, evW1h0, 0);
    k_gemm_w2<<<dim3(PQ / 256, 1, BQ), 256, 0, s3>>>(out, 0);
    cudaEventRecord(evW2h0, s3);

    k_gemm_w1<<<dim3(PQ / 256, BQ), 256, ARES_SMEM>>>(1);
    k_gemm_w2<<<dim3(PQ / 256, 1, BQ), 256>>>(out, 1);

    // Join s3 back before the harness reads out.
    cudaStreamWaitEvent(0, evW2h0, 0);
}

// round 11
// speedup vs baseline: 1.1633x; 1.1633x over previous
#include <cuda_runtime.h>
#include <cuda_fp16.h>
#include <math.h>
#include <stdint.h>

// Problem constants
#define BQ 2
#define CQ 128
#define TQ 32
#define NQ 512
#define PQ (TQ * NQ)      // 16384 points per batch
#define KQ 16
#define HIDQ 512
#define OUTC 132
#define THREEN 1536

// ---------------------------------------------------------------------------
// Device scratch (static — no allocations allowed)
// ---------------------------------------------------------------------------
__device__ float    g_xpm[BQ * PQ * CQ];   // x transposed (b,p,c), full precision
__device__ float    g_xtf[BQ * PQ * CQ];   // x transposed, tf32-rounded
__device__ float    g_q[BQ * PQ * CQ];     // q projection, fp32, point-major
__device__ uint32_t g_kvh[BQ * PQ * 128];  // per point: [0..63] kx half2, [64..127] vx half2
__device__ int      g_idx[BQ * PQ * KQ];   // neighbor composite index t_eff*N + n'
__device__ float    g_h[BQ * PQ * CQ];     // post-attn+BN h, tf32-rounded
__device__ float    g_hid[BQ * PQ * HIDQ]; // leaky(W1@h), tf32-rounded
__device__ float    g_wq[CQ * CQ], g_wk[CQ * CQ], g_wv[CQ * CQ];
__device__ float    g_w1[HIDQ * CQ], g_w2[CQ * HIDQ];

// ---------------------------------------------------------------------------
// tf32 / async helpers
// ---------------------------------------------------------------------------
__device__ __forceinline__ uint32_t f2tf(float f)
{
    uint32_t r;
    asm("cvt.rna.tf32.f32 %0, %1;" : "=r"(r) : "f"(f));
    return r;
}
__device__ __forceinline__ float f2tff(float f) { return __uint_as_float(f2tf(f)); }

__device__ __forceinline__ void mma_tf32(float c[4],
                                         uint32_t a0, uint32_t a1, uint32_t a2, uint32_t a3,
                                         uint32_t b0, uint32_t b1)
{
    asm volatile(
        "mma.sync.aligned.m16n8k8.row.col.f32.tf32.tf32.f32 "
        "{%0,%1,%2,%3},{%4,%5,%6,%7},{%8,%9},{%0,%1,%2,%3};"
        : "+f"(c[0]), "+f"(c[1]), "+f"(c[2]), "+f"(c[3])
        : "r"(a0), "r"(a1), "r"(a2), "r"(a3), "r"(b0), "r"(b1));
}

__device__ __forceinline__ void cp16(uint32_t* dst_smem, const float* src)
{
    uint32_t d = (uint32_t)__cvta_generic_to_shared(dst_smem);
    asm volatile("cp.async.cg.shared.global [%0], [%1], 16;" :: "r"(d), "l"(src));
}
__device__ __forceinline__ void cp_commit() { asm volatile("cp.async.commit_group;" ::: "memory"); }
template<int N>
__device__ __forceinline__ void cp_wait() { asm volatile("cp.async.wait_group %0;" :: "n"(N) : "memory"); }

// ---------------------------------------------------------------------------
// K_pre: round all weights to tf32 once.
// ---------------------------------------------------------------------------
__global__ void k_roundw(const float* __restrict__ Wq, const float* __restrict__ Wk,
                         const float* __restrict__ Wv, const float* __restrict__ W1,
                         const float* __restrict__ W2)
{
    int i = blockIdx.x * 256 + threadIdx.x;   // 0 .. 65535
    if (i < CQ * CQ) {
        g_wq[i] = f2tff(Wq[i]);
        g_wk[i] = f2tff(Wk[i]);
        g_wv[i] = f2tff(Wv[i]);
    }
    g_w1[i] = f2tff(W1[i]);
    g_w2[i] = f2tff(W2[i]);
}

// ---------------------------------------------------------------------------
// K0: transpose x (B,C,P) -> g_xpm (full) and g_xtf (tf32-rounded), (B,P,C).
// Also writes out channels 0..3 directly.
// ---------------------------------------------------------------------------
__global__ void k_transpose(const float* __restrict__ x, float* __restrict__ out)
{
    __shared__ float tile[32][33];
    int b = blockIdx.z;
    int p0 = blockIdx.x * 32;
    int c0 = blockIdx.y * 32;
    const float* xb = x + (size_t)b * CQ * PQ;
    int tx = threadIdx.x, ty = threadIdx.y;
#pragma unroll
    for (int i = 0; i < 32; i += 8) {
        float v = xb[(size_t)(c0 + ty + i) * PQ + p0 + tx];
        tile[ty + i][tx] = v;
        if (c0 == 0 && (ty + i) < 4)
            out[(size_t)b * OUTC * PQ + (size_t)(ty + i) * PQ + p0 + tx] = v;
    }
    __syncthreads();
    float* op  = g_xpm + (size_t)b * PQ * CQ;
    float* op2 = g_xtf + (size_t)b * PQ * CQ;
#pragma unroll
    for (int i = 0; i < 32; i += 8) {
        float v = tile[tx][ty + i];
        size_t o = (size_t)(p0 + ty + i) * CQ + c0 + tx;
        op[o]  = v;
        op2[o] = f2tff(v);
    }
}

// ---------------------------------------------------------------------------
// K1: top-K neighbor selection (exact; round-8 algorithm, full batch grid).
// ---------------------------------------------------------------------------
__global__ void __launch_bounds__(256) k_topk(const float* __restrict__ x)
{
    int t = blockIdx.x, b = blockIdx.y, z = blockIdx.z;
    __shared__ float sc[3][THREEN];
    const float* xb = x + (size_t)b * CQ * PQ;
    int tid = threadIdx.x;

    for (int i = tid; i < 3 * THREEN; i += 256) {
        int c = i / THREEN, m = i % THREEN;
        int j = m >> 9, nn = m & 511;
        int te = t - 1 + j;
        te = te < 0 ? 0 : (te > TQ - 1 ? TQ - 1 : te);
        sc[c][m] = xb[(size_t)c * PQ + te * NQ + nn];
    }
    __syncthreads();

    const unsigned FULL = 0xffffffffu;
    const float FINF = __int_as_float(0x7f800000);
    int lane = tid & 31, w = tid >> 5;

    for (int i = 0; i < 8; i++) {
        int n = z * 64 + w * 8 + i;
        float a0 = sc[0][512 + n], a1 = sc[1][512 + n], a2 = sc[2][512 + n];

        float e0 = FINF, e1 = FINF, e2 = FINF, e3 = FINF;
        int   q0 = 0,    q1 = 0,    q2 = 0,    q3 = 0;
#pragma unroll
        for (int jj = 0; jj < 48; jj++) {
            int m = jj * 32 + lane;
            float dx = sc[0][m] - a0;
            float dy = sc[1][m] - a1;
            float dz = sc[2][m] - a2;
            float dc = dx * dx + dy * dy + dz * dz;
            bool l0 = dc < e0, l1 = dc < e1, l2 = dc < e2, l3 = dc < e3;
            e3 = l3 ? (l2 ? e2 : dc) : e3;  q3 = l3 ? (l2 ? q2 : m) : q3;
            e2 = l2 ? (l1 ? e1 : dc) : e2;  q2 = l2 ? (l1 ? q1 : m) : q2;
            e1 = l1 ? (l0 ? e0 : dc) : e1;  q1 = l1 ? (l0 ? q0 : m) : q1;
            e0 = l0 ? dc : e0;              q0 = l0 ? m : q0;
        }

        int ptr = 0;
        bool bad = false;
        int* orow = g_idx + ((size_t)(b * TQ + t) * NQ + n) * KQ;
#pragma unroll
        for (int it = 0; it < KQ; it++) {
            bad |= __any_sync(FULL, ptr >= 4);
            unsigned long long mykey =
                ((unsigned long long)__float_as_uint(e0) << 32) | (unsigned)q0;
            unsigned long long k = mykey;
#pragma unroll
            for (int off = 16; off; off >>= 1) {
                unsigned long long o = __shfl_xor_sync(FULL, k, off);
                if (o < k) k = o;
            }
            if (mykey == k) {
                e0 = e1; q0 = q1; e1 = e2; q1 = q2; e2 = e3; q2 = q3;
                e3 = FINF; q3 = 0; ptr++;
            }
            if (lane == 0) {
                int m = (int)(k & 0xffffffffu);
                int jwin = m >> 9, nwin = m & 511;
                int te = t - 1 + jwin;
                te = te < 0 ? 0 : (te > TQ - 1 ? TQ - 1 : te);
                orow[it] = te * NQ + nwin;
            }
        }

        if (bad) {
            unsigned long long removed = 0ull;
            for (int it = 0; it < KQ; it++) {
                float best = 3.4e38f;
                int bj = 0;
#pragma unroll
                for (int jj = 0; jj < 48; jj++) {
                    int m = jj * 32 + lane;
                    float dx = sc[0][m] - a0;
                    float dy = sc[1][m] - a1;
                    float dz = sc[2][m] - a2;
                    float dc = dx * dx + dy * dy + dz * dz;
                    bool alive = !(removed & (1ull << jj));
                    if (alive && dc < best) { best = dc; bj = jj; }
                }
                int bm = bj * 32 + lane;
#pragma unroll
                for (int off = 16; off; off >>= 1) {
                    float od = __shfl_xor_sync(FULL, best, off);
                    int   om = __shfl_xor_sync(FULL, bm, off);
                    if (od < best || (od == best && om < bm)) { best = od; bm = om; }
                }
                if ((bm & 31) == lane) removed |= (1ull << (bm >> 5));
                if (lane == 0) {
                    int jwin = bm >> 9, nwin = bm & 511;
                    int te = t - 1 + jwin;
                    te = te < 0 ? 0 : (te > TQ - 1 ? TQ - 1 : te);
                    orow[it] = te * NQ + nwin;
                }
            }
        }
    }
}

// ---------------------------------------------------------------------------
// Streaming tf32 GEMM core (used by W2).
// ---------------------------------------------------------------------------
template<int CIN>
__device__ __forceinline__ void gemm_core(const float* __restrict__ A,
                                          const float* __restrict__ W,
                                          float acc[4][4][4], int tid)
{
    constexpr int KC = 16;
    constexpr int NCH = CIN / KC;
    __shared__ uint32_t As[2][128 * 20];
    __shared__ uint32_t Bs[2][128 * 20];

    const int lane = tid & 31, wid = tid >> 5;
    const int gid = lane >> 2, tig = lane & 3;
    const int mbase = (wid & 1) * 64, nbase = (wid >> 1) * 32;

    const int r0 = tid >> 2, s0 = (tid & 3) * 4;
    const int r1 = r0 + 64;

    {
        cp16(&As[0][r0 * 20 + s0], A + (size_t)r0 * CIN + s0);
        cp16(&As[0][r1 * 20 + s0], A + (size_t)r1 * CIN + s0);
        cp16(&Bs[0][r0 * 20 + s0], W + (size_t)r0 * CIN + s0);
        cp16(&Bs[0][r1 * 20 + s0], W + (size_t)r1 * CIN + s0);
        cp_commit();
    }

#pragma unroll 1
    for (int kc = 0; kc < NCH; kc++) {
        const int st = kc & 1;
        cp_wait<0>();
        __syncthreads();
        if (kc + 1 < NCH) {
            const int k0g = (kc + 1) * KC;
            cp16(&As[st ^ 1][r0 * 20 + s0], A + (size_t)r0 * CIN + k0g + s0);
            cp16(&As[st ^ 1][r1 * 20 + s0], A + (size_t)r1 * CIN + k0g + s0);
            cp16(&Bs[st ^ 1][r0 * 20 + s0], W + (size_t)r0 * CIN + k0g + s0);
            cp16(&Bs[st ^ 1][r1 * 20 + s0], W + (size_t)r1 * CIN + k0g + s0);
            cp_commit();
        }

#pragma unroll
        for (int ks = 0; ks < 2; ks++) {
            const int k0 = ks * 8;
            uint32_t af[4][4], bf[4][2];
#pragma unroll
            for (int mt = 0; mt < 4; mt++) {
                int m = mbase + mt * 16 + gid;
                af[mt][0] = As[st][m * 20 + k0 + tig];
                af[mt][1] = As[st][(m + 8) * 20 + k0 + tig];
                af[mt][2] = As[st][m * 20 + k0 + 4 + tig];
                af[mt][3] = As[st][(m + 8) * 20 + k0 + 4 + tig];
            }
#pragma unroll
            for (int nt = 0; nt < 4; nt++) {
                int n = nbase + nt * 8 + gid;
                bf[nt][0] = Bs[st][n * 20 + k0 + tig];
                bf[nt][1] = Bs[st][n * 20 + k0 + 4 + tig];
            }
#pragma unroll
            for (int mt = 0; mt < 4; mt++)
#pragma unroll
                for (int nt = 0; nt < 4; nt++)
                    mma_tf32(acc[mt][nt], af[mt][0], af[mt][1], af[mt][2], af[mt][3],
                             bf[nt][0], bf[nt][1]);
        }
    }
    __syncthreads();
}

// ---------------------------------------------------------------------------
// A-resident GEMM compute (unchanged).
// ---------------------------------------------------------------------------
__device__ __forceinline__ void gemm_Ares_pass(const uint32_t* __restrict__ As,
                                               uint32_t* __restrict__ Bs,
                                               const float* __restrict__ W,
                                               float acc[4][4][4],
                                               int tid)
{
    const int lane = tid & 31, wid = tid >> 5;
    const int gid = lane >> 2, tig = lane & 3;
    const int mbase = (wid & 1) * 64, nbase = (wid >> 1) * 32;
    const int r0 = tid >> 2, s0 = (tid & 3) * 4;
    const int r1 = r0 + 64;

    cp16(&Bs[r0 * 20 + s0], W + (size_t)r0 * CQ + s0);
    cp16(&Bs[r1 * 20 + s0], W + (size_t)r1 * CQ + s0);
    cp_commit();

#pragma unroll 1
    for (int kc = 0; kc < 8; kc++) {
        const int st = kc & 1;
        cp_wait<0>();
        __syncthreads();
        if (kc + 1 < 8) {
            const int k0g = (kc + 1) * 16;
            uint32_t* Bd = Bs + (st ^ 1) * (128 * 20);
            cp16(&Bd[r0 * 20 + s0], W + (size_t)r0 * CQ + k0g + s0);
            cp16(&Bd[r1 * 20 + s0], W + (size_t)r1 * CQ + k0g + s0);
            cp_commit();
        }
        const uint32_t* Bc = Bs + st * (128 * 20);

#pragma unroll
        for (int ks = 0; ks < 2; ks++) {
            const int ka = kc * 16 + ks * 8;
            const int kb = ks * 8;
            uint32_t af[4][4], bf[4][2];
#pragma unroll
            for (int mt = 0; mt < 4; mt++) {
                int m = mbase + mt * 16 + gid;
                af[mt][0] = As[m * 132 + ka + tig];
                af[mt][1] = As[(m + 8) * 132 + ka + tig];
                af[mt][2] = As[m * 132 + ka + 4 + tig];
                af[mt][3] = As[(m + 8) * 132 + ka + 4 + tig];
            }
#pragma unroll
            for (int nt = 0; nt < 4; nt++) {
                int n = nbase + nt * 8 + gid;
                bf[nt][0] = Bc[n * 20 + kb + tig];
                bf[nt][1] = Bc[n * 20 + kb + 4 + tig];
            }
#pragma unroll
            for (int mt = 0; mt < 4; mt++)
#pragma unroll
                for (int nt = 0; nt < 4; nt++)
                    mma_tf32(acc[mt][nt], af[mt][0], af[mt][1], af[mt][2], af[mt][3],
                             bf[nt][0], bf[nt][1]);
        }
    }
}

#define ARES_SMEM ((128 * 132 + 2 * 128 * 20) * 4)   // 88064 B

// K2: merged QKV projection. grid (PQ/128, B).
// q -> g_q (fp32); kx/vx -> g_kvh (half2 packed).
__global__ void __launch_bounds__(256) k_gemm_qkv()
{
    extern __shared__ uint32_t sm[];
    uint32_t* As = sm;                    // [128][132]
    uint32_t* Bs = sm + 128 * 132;        // [2][128][20]

    const int b = blockIdx.y;
    const int p0 = blockIdx.x * 128;
    const int tid = threadIdx.x;
    const float* A = g_xtf + (size_t)(b * PQ + p0) * CQ;

#pragma unroll
    for (int it = 0; it < 16; it++) {
        int id = tid + it * 256;
        int r = id >> 5, seg = (id & 31) * 4;
        cp16(&As[r * 132 + seg], A + (size_t)r * CQ + seg);
    }
    cp_commit();

    const int lane = tid & 31, wid = tid >> 5;
    const int gid = lane >> 2, tig = lane & 3;

#pragma unroll 1
    for (int cq = 0; cq < 3; cq++) {
        const float* W = (cq == 0) ? g_wq : ((cq == 1) ? g_wk : g_wv);
        float acc[4][4][4] = {};
        gemm_Ares_pass(As, Bs, W, acc, tid);

        const int prow = b * PQ + p0 + (wid & 1) * 64;
        if (cq == 0) {
            float* base = g_q + (size_t)prow * CQ + (wid >> 1) * 32;
#pragma unroll
            for (int mt = 0; mt < 4; mt++) {
                int r = mt * 16 + gid;
#pragma unroll
                for (int nt = 0; nt < 4; nt++) {
                    int c = nt * 8 + tig * 2;
                    *(float2*)(base + (size_t)r * CQ + c)       = make_float2(acc[mt][nt][0], acc[mt][nt][1]);
                    *(float2*)(base + (size_t)(r + 8) * CQ + c) = make_float2(acc[mt][nt][2], acc[mt][nt][3]);
                }
            }
        } else {
            // half2 packed: per point row of 128 u32 = [kx 64 | vx 64]
            uint32_t* base = g_kvh + (size_t)prow * 128 + (cq - 1) * 64 + (wid >> 1) * 16;
#pragma unroll
            for (int mt = 0; mt < 4; mt++) {
                int r = mt * 16 + gid;
#pragma unroll
                for (int nt = 0; nt < 4; nt++) {
                    int h2i = nt * 4 + tig;
                    __half2 lo = __floats2half2_rn(acc[mt][nt][0], acc[mt][nt][1]);
                    __half2 hi = __floats2half2_rn(acc[mt][nt][2], acc[mt][nt][3]);
                    base[(size_t)r * 128 + h2i]       = *(uint32_t*)&lo;
                    base[(size_t)(r + 8) * 128 + h2i] = *(uint32_t*)&hi;
                }
            }
        }
    }
}

// ---------------------------------------------------------------------------
// K3: attention + residual + BN. fp16 K/V gathers (8B/lane), fp32 math.
// ---------------------------------------------------------------------------
__global__ void __launch_bounds__(256) k_attn(const float* __restrict__ gamma,
                                              const float* __restrict__ beta,
                                              const float* __restrict__ mean,
                                              const float* __restrict__ var)
{
    __shared__ float s_scale[CQ], s_shift[CQ];
    int tid = threadIdx.x;
    if (tid < CQ) {
        float sc = gamma[tid] * rsqrtf(var[tid] + 1e-5f);
        s_scale[tid] = sc;
        s_shift[tid] = beta[tid] - mean[tid] * sc;
    }
    __syncthreads();

    int lane = tid & 31, w = tid >> 5;
    const float rs = 0.17677669529663687f; // 1/sqrt(32)

    for (int i = 0; i < 8; i++) {
        int g = blockIdx.x * 64 + w * 8 + i;
        int b = g >> 14;
        int bbase = b << 14;

        float4 qv = ((const float4*)(g_q + (size_t)g * CQ))[lane];

        const uint32_t* kvrow = g_kvh + (size_t)g * 128;
        uint2 su = *(const uint2*)(kvrow + 2 * lane);
        uint2 vu = *(const uint2*)(kvrow + 64 + 2 * lane);
        float2 k0 = __half22float2(*(__half2*)&su.x);
        float2 k1 = __half22float2(*(__half2*)&su.y);
        float2 v0 = __half22float2(*(__half2*)&vu.x);
        float2 v1 = __half22float2(*(__half2*)&vu.y);

        const int* irow = g_idx + (size_t)g * KQ;
        int myidx = irow[lane & 15];

        float dself;
        {
            float p = qv.x * k0.x + qv.y * k0.y + qv.z * k1.x + qv.w * k1.y;
            p += __shfl_xor_sync(0xffffffffu, p, 1);
            p += __shfl_xor_sync(0xffffffffu, p, 2);
            p += __shfl_xor_sync(0xffffffffu, p, 4);
            dself = p;
        }

        float e[16];
#pragma unroll
        for (int k = 0; k < 16; k++) {
            int nb = __shfl_sync(0xffffffffu, myidx, k);
            uint2 ku = *(const uint2*)(g_kvh + (size_t)(bbase + nb) * 128 + 2 * lane);
            float2 f0 = __half22float2(*(__half2*)&ku.x);
            float2 f1 = __half22float2(*(__half2*)&ku.y);
            float p = qv.x * f0.x + qv.y * f0.y + qv.z * f1.x + qv.w * f1.y;
            p += __shfl_xor_sync(0xffffffffu, p, 1);
            p += __shfl_xor_sync(0xffffffffu, p, 2);
            p += __shfl_xor_sync(0xffffffffu, p, 4);
            e[k] = (dself - p) * rs;
        }

        float mx = e[0];
#pragma unroll
        for (int k = 1; k < 16; k++) mx = fmaxf(mx, e[k]);
        float s = 0.f;
#pragma unroll
        for (int k = 0; k < 16; k++) { e[k] = __expf(e[k] - mx); s += e[k]; }
        float inv = 1.0f / s;

        float4 acc = make_float4(v0.x, v0.y, v1.x, v1.y);  // sum(attn)=1 -> self term
#pragma unroll
        for (int k = 0; k < 16; k++) {
            int nb = __shfl_sync(0xffffffffu, myidx, k);
            uint2 wu = *(const uint2*)(g_kvh + (size_t)(bbase + nb) * 128 + 64 + 2 * lane);
            float2 f0 = __half22float2(*(__half2*)&wu.x);
            float2 f1 = __half22float2(*(__half2*)&wu.y);
            float a = e[k] * inv;
            acc.x -= a * f0.x; acc.y -= a * f0.y;
            acc.z -= a * f1.x; acc.w -= a * f1.y;
        }

        const float4* xp = (const float4*)(g_xpm + (size_t)g * CQ);
        float4 xv = xp[lane];
        int c = lane * 4;
        float4 hv;
        hv.x = f2tff((xv.x + acc.x) * s_scale[c + 0] + s_shift[c + 0]);
        hv.y = f2tff((xv.y + acc.y) * s_scale[c + 1] + s_shift[c + 1]);
        hv.z = f2tff((xv.z + acc.z) * s_scale[c + 2] + s_shift[c + 2]);
        hv.w = f2tff((xv.w + acc.w) * s_scale[c + 3] + s_shift[c + 3]);
        ((float4*)(g_h + (size_t)g * CQ))[lane] = hv;
    }
}

// K4: W1 with resident h tile. grid (PQ/128, B).
__global__ void __launch_bounds__(256) k_gemm_w1()
{
    extern __shared__ uint32_t sm[];
    uint32_t* As = sm;
    uint32_t* Bs = sm + 128 * 132;

    const int b = blockIdx.y;
    const int p0 = blockIdx.x * 128;
    const int tid = threadIdx.x;
    const float* A = g_h + (size_t)(b * PQ + p0) * CQ;

#pragma unroll
    for (int it = 0; it < 16; it++) {
        int id = tid + it * 256;
        int r = id >> 5, seg = (id & 31) * 4;
        cp16(&As[r * 132 + seg], A + (size_t)r * CQ + seg);
    }
    cp_commit();

    const int lane = tid & 31, wid = tid >> 5;
    const int gid = lane >> 2, tig = lane & 3;

#pragma unroll 1
    for (int nt4 = 0; nt4 < 4; nt4++) {
        const int co0 = nt4 * 128;
        float acc[4][4][4] = {};
        gemm_Ares_pass(As, Bs, g_w1 + (size_t)co0 * CQ, acc, tid);

        float* base = g_hid + (size_t)(b * PQ + p0 + (wid & 1) * 64) * HIDQ
                    + co0 + (wid >> 1) * 32;
#pragma unroll
        for (int mt = 0; mt < 4; mt++) {
            int r = mt * 16 + gid;
#pragma unroll
            for (int nt = 0; nt < 4; nt++) {
                int c = nt * 8 + tig * 2;
                float v0 = acc[mt][nt][0], v1 = acc[mt][nt][1];
                float v2 = acc[mt][nt][2], v3 = acc[mt][nt][3];
                v0 = f2tff(v0 > 0.f ? v0 : 0.2f * v0);
                v1 = f2tff(v1 > 0.f ? v1 : 0.2f * v1);
                v2 = f2tff(v2 > 0.f ? v2 : 0.2f * v2);
                v3 = f2tff(v3 > 0.f ? v3 : 0.2f * v3);
                *(float2*)(base + (size_t)r * HIDQ + c)       = make_float2(v0, v1);
                *(float2*)(base + (size_t)(r + 8) * HIDQ + c) = make_float2(v2, v3);
            }
        }
    }
}

// K5: y = W2 @ hid, channel-major into d_out at channel offset 4. grid (PQ/128,1,B).
__global__ void __launch_bounds__(256) k_gemm_w2(float* __restrict__ out)
{
    int b = blockIdx.z;
    int p0 = blockIdx.x * 128;

    float acc[4][4][4] = {};
    gemm_core<HIDQ>(g_hid + (size_t)(b * PQ + p0) * HIDQ, g_w2, acc, threadIdx.x);

    const int lane = threadIdx.x & 31, wid = threadIdx.x >> 5;
    const int gid = lane >> 2, tig = lane & 3;
    float* ob = out + (size_t)b * OUTC * PQ + (size_t)4 * PQ;
    int rbase = p0 + (wid & 1) * 64;
    int cbase = (wid >> 1) * 32;
#pragma unroll
    for (int mt = 0; mt < 4; mt++) {
        int r = rbase + mt * 16 + gid;
#pragma unroll
        for (int nt = 0; nt < 4; nt++) {
            int c = cbase + nt * 8 + tig * 2;
            ob[(size_t)c * PQ + r]           = acc[mt][nt][0];
            ob[(size_t)(c + 1) * PQ + r]     = acc[mt][nt][1];
            ob[(size_t)c * PQ + r + 8]       = acc[mt][nt][2];
            ob[(size_t)(c + 1) * PQ + r + 8] = acc[mt][nt][3];
        }
    }
}

// ---------------------------------------------------------------------------
extern "C" void kernel_launch(void* const* d_in, const int* in_sizes, int n_in,
                              void* d_out, int out_size)
{
    const float* x     = (const float*)d_in[0];
    const float* Wq    = (const float*)d_in[1];
    const float* Wk    = (const float*)d_in[2];
    const float* Wv    = (const float*)d_in[3];
    const float* W1    = (const float*)d_in[4];
    const float* W2    = (const float*)d_in[5];
    const float* gamma = (const float*)d_in[6];
    const float* beta  = (const float*)d_in[7];
    const float* mean  = (const float*)d_in[8];
    const float* var   = (const float*)d_in[9];
    float* out = (float*)d_out;

    static cudaStream_t s2;
    static cudaEvent_t evFork, evJoin;
    static int init_done = 0;
    if (!init_done) {
        cudaFuncSetAttribute(k_gemm_qkv, cudaFuncAttributeMaxDynamicSharedMemorySize, ARES_SMEM);
        cudaFuncSetAttribute(k_gemm_w1,  cudaFuncAttributeMaxDynamicSharedMemorySize, ARES_SMEM);
        cudaStreamCreateWithFlags(&s2, cudaStreamNonBlocking);
        cudaEventCreateWithFlags(&evFork, cudaEventDisableTiming);
        cudaEventCreateWithFlags(&evJoin, cudaEventDisableTiming);
        init_done = 1;
    }

    // Round-8 structure: single fork for topk, everything else serial full-grid.
    cudaEventRecord(evFork, 0);
    cudaStreamWaitEvent(s2, evFork, 0);
    k_topk<<<dim3(TQ, BQ, 8), 256, 0, s2>>>(x);
    cudaEventRecord(evJoin, s2);

    k_roundw<<<256, 256>>>(Wq, Wk, Wv, W1, W2);
    k_transpose<<<dim3(PQ / 32, CQ / 32, BQ), dim3(32, 8)>>>(x, out);
    k_gemm_qkv<<<dim3(PQ / 128, BQ), 256, ARES_SMEM>>>();

    cudaStreamWaitEvent(0, evJoin, 0);
    k_attn<<<dim3((BQ * PQ) / 64, 1, 1), 256>>>(gamma, beta, mean, var);
    k_gemm_w1<<<dim3(PQ / 128, BQ), 256, ARES_SMEM>>>();
    k_gemm_w2<<<dim3(PQ / 128, 1, BQ), 256>>>(out);
}

// round 12
// speedup vs baseline: 1.2689x; 1.0908x over previous
#include <cuda_runtime.h>
#include <cuda_fp16.h>
#include <math.h>
#include <stdint.h>

// Problem constants
#define BQ 2
#define CQ 128
#define TQ 32
#define NQ 512
#define PQ (TQ * NQ)      // 16384 points per batch
#define KQ 16
#define HIDQ 512
#define OUTC 132
#define THREEN 1536

// ---------------------------------------------------------------------------
// Device scratch (static — no allocations allowed)
// ---------------------------------------------------------------------------
__device__ float    g_xpm[BQ * PQ * CQ];   // x transposed (b,p,c), full precision
__device__ float    g_xtf[BQ * PQ * CQ];   // x transposed, tf32-rounded
__device__ float    g_q[BQ * PQ * CQ];     // q projection, fp32, point-major
__device__ uint32_t g_kvh[BQ * PQ * 128];  // per point: [0..63] kx half2, [64..127] vx half2
__device__ int      g_idx[BQ * PQ * KQ];   // neighbor composite index t_eff*N + n'
__device__ float    g_h[BQ * PQ * CQ];     // post-attn+BN h, tf32-rounded (W1 input)
__device__ uint32_t g_hidh[BQ * PQ * (HIDQ / 2)];  // leaky(W1@h), half2 packed (W2 input)
__device__ float    g_wq[CQ * CQ], g_wk[CQ * CQ], g_wv[CQ * CQ];
__device__ float    g_w1[HIDQ * CQ];
__device__ uint32_t g_w2h[(CQ * HIDQ) / 2];        // W2 half2 packed along k

// ---------------------------------------------------------------------------
// tf32 / fp16 / async helpers
// ---------------------------------------------------------------------------
__device__ __forceinline__ uint32_t f2tf(float f)
{
    uint32_t r;
    asm("cvt.rna.tf32.f32 %0, %1;" : "=r"(r) : "f"(f));
    return r;
}
__device__ __forceinline__ float f2tff(float f) { return __uint_as_float(f2tf(f)); }

__device__ __forceinline__ void mma_tf32(float c[4],
                                         uint32_t a0, uint32_t a1, uint32_t a2, uint32_t a3,
                                         uint32_t b0, uint32_t b1)
{
    asm volatile(
        "mma.sync.aligned.m16n8k8.row.col.f32.tf32.tf32.f32 "
        "{%0,%1,%2,%3},{%4,%5,%6,%7},{%8,%9},{%0,%1,%2,%3};"
        : "+f"(c[0]), "+f"(c[1]), "+f"(c[2]), "+f"(c[3])
        : "r"(a0), "r"(a1), "r"(a2), "r"(a3), "r"(b0), "r"(b1));
}

__device__ __forceinline__ void mma_f16(float c[4],
                                        uint32_t a0, uint32_t a1, uint32_t a2, uint32_t a3,
                                        uint32_t b0, uint32_t b1)
{
    asm volatile(
        "mma.sync.aligned.m16n8k16.row.col.f32.f16.f16.f32 "
        "{%0,%1,%2,%3},{%4,%5,%6,%7},{%8,%9},{%0,%1,%2,%3};"
        : "+f"(c[0]), "+f"(c[1]), "+f"(c[2]), "+f"(c[3])
        : "r"(a0), "r"(a1), "r"(a2), "r"(a3), "r"(b0), "r"(b1));
}

__device__ __forceinline__ void cp16(uint32_t* dst_smem, const void* src)
{
    uint32_t d = (uint32_t)__cvta_generic_to_shared(dst_smem);
    asm volatile("cp.async.cg.shared.global [%0], [%1], 16;" :: "r"(d), "l"(src));
}
__device__ __forceinline__ void cp_commit() { asm volatile("cp.async.commit_group;" ::: "memory"); }
template<int N>
__device__ __forceinline__ void cp_wait() { asm volatile("cp.async.wait_group %0;" :: "n"(N) : "memory"); }

// ---------------------------------------------------------------------------
// K_pre: round weights (tf32 for Wq/Wk/Wv/W1; packed fp16 for W2).
// ---------------------------------------------------------------------------
__global__ void k_roundw(const float* __restrict__ Wq, const float* __restrict__ Wk,
                         const float* __restrict__ Wv, const float* __restrict__ W1,
                         const float* __restrict__ W2)
{
    int i = blockIdx.x * 256 + threadIdx.x;   // 0 .. 65535
    if (i < CQ * CQ) {
        g_wq[i] = f2tff(Wq[i]);
        g_wk[i] = f2tff(Wk[i]);
        g_wv[i] = f2tff(Wv[i]);
    }
    g_w1[i] = f2tff(W1[i]);
    if (i < (CQ * HIDQ) / 2) {
        __half2 h = __floats2half2_rn(W2[2 * i], W2[2 * i + 1]);
        g_w2h[i] = *(uint32_t*)&h;
    }
}

// ---------------------------------------------------------------------------
// K0: transpose x (B,C,P) -> g_xpm (full) and g_xtf (tf32-rounded), (B,P,C).
// Also writes out channels 0..3 directly.
// ---------------------------------------------------------------------------
__global__ void k_transpose(const float* __restrict__ x, float* __restrict__ out)
{
    __shared__ float tile[32][33];
    int b = blockIdx.z;
    int p0 = blockIdx.x * 32;
    int c0 = blockIdx.y * 32;
    const float* xb = x + (size_t)b * CQ * PQ;
    int tx = threadIdx.x, ty = threadIdx.y;
#pragma unroll
    for (int i = 0; i < 32; i += 8) {
        float v = xb[(size_t)(c0 + ty + i) * PQ + p0 + tx];
        tile[ty + i][tx] = v;
        if (c0 == 0 && (ty + i) < 4)
            out[(size_t)b * OUTC * PQ + (size_t)(ty + i) * PQ + p0 + tx] = v;
    }
    __syncthreads();
    float* op  = g_xpm + (size_t)b * PQ * CQ;
    float* op2 = g_xtf + (size_t)b * PQ * CQ;
#pragma unroll
    for (int i = 0; i < 32; i += 8) {
        float v = tile[tx][ty + i];
        size_t o = (size_t)(p0 + ty + i) * CQ + c0 + tx;
        op[o]  = v;
        op2[o] = f2tff(v);
    }
}

// ---------------------------------------------------------------------------
// K1: top-K neighbor selection (exact; unchanged).
// ---------------------------------------------------------------------------
__global__ void __launch_bounds__(256) k_topk(const float* __restrict__ x)
{
    int t = blockIdx.x, b = blockIdx.y, z = blockIdx.z;
    __shared__ float sc[3][THREEN];
    const float* xb = x + (size_t)b * CQ * PQ;
    int tid = threadIdx.x;

    for (int i = tid; i < 3 * THREEN; i += 256) {
        int c = i / THREEN, m = i % THREEN;
        int j = m >> 9, nn = m & 511;
        int te = t - 1 + j;
        te = te < 0 ? 0 : (te > TQ - 1 ? TQ - 1 : te);
        sc[c][m] = xb[(size_t)c * PQ + te * NQ + nn];
    }
    __syncthreads();

    const unsigned FULL = 0xffffffffu;
    const float FINF = __int_as_float(0x7f800000);
    int lane = tid & 31, w = tid >> 5;

    for (int i = 0; i < 8; i++) {
        int n = z * 64 + w * 8 + i;
        float a0 = sc[0][512 + n], a1 = sc[1][512 + n], a2 = sc[2][512 + n];

        float e0 = FINF, e1 = FINF, e2 = FINF, e3 = FINF;
        int   q0 = 0,    q1 = 0,    q2 = 0,    q3 = 0;
#pragma unroll
        for (int jj = 0; jj < 48; jj++) {
            int m = jj * 32 + lane;
            float dx = sc[0][m] - a0;
            float dy = sc[1][m] - a1;
            float dz = sc[2][m] - a2;
            float dc = dx * dx + dy * dy + dz * dz;
            bool l0 = dc < e0, l1 = dc < e1, l2 = dc < e2, l3 = dc < e3;
            e3 = l3 ? (l2 ? e2 : dc) : e3;  q3 = l3 ? (l2 ? q2 : m) : q3;
            e2 = l2 ? (l1 ? e1 : dc) : e2;  q2 = l2 ? (l1 ? q1 : m) : q2;
            e1 = l1 ? (l0 ? e0 : dc) : e1;  q1 = l1 ? (l0 ? q0 : m) : q1;
            e0 = l0 ? dc : e0;              q0 = l0 ? m : q0;
        }

        int ptr = 0;
        bool bad = false;
        int* orow = g_idx + ((size_t)(b * TQ + t) * NQ + n) * KQ;
#pragma unroll
        for (int it = 0; it < KQ; it++) {
            bad |= __any_sync(FULL, ptr >= 4);
            unsigned long long mykey =
                ((unsigned long long)__float_as_uint(e0) << 32) | (unsigned)q0;
            unsigned long long k = mykey;
#pragma unroll
            for (int off = 16; off; off >>= 1) {
                unsigned long long o = __shfl_xor_sync(FULL, k, off);
                if (o < k) k = o;
            }
            if (mykey == k) {
                e0 = e1; q0 = q1; e1 = e2; q1 = q2; e2 = e3; q2 = q3;
                e3 = FINF; q3 = 0; ptr++;
            }
            if (lane == 0) {
                int m = (int)(k & 0xffffffffu);
                int jwin = m >> 9, nwin = m & 511;
                int te = t - 1 + jwin;
                te = te < 0 ? 0 : (te > TQ - 1 ? TQ - 1 : te);
                orow[it] = te * NQ + nwin;
            }
        }

        if (bad) {
            unsigned long long removed = 0ull;
            for (int it = 0; it < KQ; it++) {
                float best = 3.4e38f;
                int bj = 0;
#pragma unroll
                for (int jj = 0; jj < 48; jj++) {
                    int m = jj * 32 + lane;
                    float dx = sc[0][m] - a0;
                    float dy = sc[1][m] - a1;
                    float dz = sc[2][m] - a2;
                    float dc = dx * dx + dy * dy + dz * dz;
                    bool alive = !(removed & (1ull << jj));
                    if (alive && dc < best) { best = dc; bj = jj; }
                }
                int bm = bj * 32 + lane;
#pragma unroll
                for (int off = 16; off; off >>= 1) {
                    float od = __shfl_xor_sync(FULL, best, off);
                    int   om = __shfl_xor_sync(FULL, bm, off);
                    if (od < best || (od == best && om < bm)) { best = od; bm = om; }
                }
                if ((bm & 31) == lane) removed |= (1ull << (bm >> 5));
                if (lane == 0) {
                    int jwin = bm >> 9, nwin = bm & 511;
                    int te = t - 1 + jwin;
                    te = te < 0 ? 0 : (te > TQ - 1 ? TQ - 1 : te);
                    orow[it] = te * NQ + nwin;
                }
            }
        }
    }
}

// ---------------------------------------------------------------------------
// A-resident tf32 GEMM compute (unchanged; used by qkv and w1).
// ---------------------------------------------------------------------------
__device__ __forceinline__ void gemm_Ares_pass(const uint32_t* __restrict__ As,
                                               uint32_t* __restrict__ Bs,
                                               const float* __restrict__ W,
                                               float acc[4][4][4],
                                               int tid)
{
    const int lane = tid & 31, wid = tid >> 5;
    const int gid = lane >> 2, tig = lane & 3;
    const int mbase = (wid & 1) * 64, nbase = (wid >> 1) * 32;
    const int r0 = tid >> 2, s0 = (tid & 3) * 4;
    const int r1 = r0 + 64;

    cp16(&Bs[r0 * 20 + s0], W + (size_t)r0 * CQ + s0);
    cp16(&Bs[r1 * 20 + s0], W + (size_t)r1 * CQ + s0);
    cp_commit();

#pragma unroll 1
    for (int kc = 0; kc < 8; kc++) {
        const int st = kc & 1;
        cp_wait<0>();
        __syncthreads();
        if (kc + 1 < 8) {
            const int k0g = (kc + 1) * 16;
            uint32_t* Bd = Bs + (st ^ 1) * (128 * 20);
            cp16(&Bd[r0 * 20 + s0], W + (size_t)r0 * CQ + k0g + s0);
            cp16(&Bd[r1 * 20 + s0], W + (size_t)r1 * CQ + k0g + s0);
            cp_commit();
        }
        const uint32_t* Bc = Bs + st * (128 * 20);

#pragma unroll
        for (int ks = 0; ks < 2; ks++) {
            const int ka = kc * 16 + ks * 8;
            const int kb = ks * 8;
            uint32_t af[4][4], bf[4][2];
#pragma unroll
            for (int mt = 0; mt < 4; mt++) {
                int m = mbase + mt * 16 + gid;
                af[mt][0] = As[m * 132 + ka + tig];
                af[mt][1] = As[(m + 8) * 132 + ka + tig];
                af[mt][2] = As[m * 132 + ka + 4 + tig];
                af[mt][3] = As[(m + 8) * 132 + ka + 4 + tig];
            }
#pragma unroll
            for (int nt = 0; nt < 4; nt++) {
                int n = nbase + nt * 8 + gid;
                bf[nt][0] = Bc[n * 20 + kb + tig];
                bf[nt][1] = Bc[n * 20 + kb + 4 + tig];
            }
#pragma unroll
            for (int mt = 0; mt < 4; mt++)
#pragma unroll
                for (int nt = 0; nt < 4; nt++)
                    mma_tf32(acc[mt][nt], af[mt][0], af[mt][1], af[mt][2], af[mt][3],
                             bf[nt][0], bf[nt][1]);
        }
    }
}

#define ARES_SMEM ((128 * 132 + 2 * 128 * 20) * 4)   // 88064 B

// K2: merged QKV projection (unchanged from round 11).
__global__ void __launch_bounds__(256) k_gemm_qkv()
{
    extern __shared__ uint32_t sm[];
    uint32_t* As = sm;                    // [128][132]
    uint32_t* Bs = sm + 128 * 132;        // [2][128][20]

    const int b = blockIdx.y;
    const int p0 = blockIdx.x * 128;
    const int tid = threadIdx.x;
    const float* A = g_xtf + (size_t)(b * PQ + p0) * CQ;

#pragma unroll
    for (int it = 0; it < 16; it++) {
        int id = tid + it * 256;
        int r = id >> 5, seg = (id & 31) * 4;
        cp16(&As[r * 132 + seg], A + (size_t)r * CQ + seg);
    }
    cp_commit();

    const int lane = tid & 31, wid = tid >> 5;
    const int gid = lane >> 2, tig = lane & 3;

#pragma unroll 1
    for (int cq = 0; cq < 3; cq++) {
        const float* W = (cq == 0) ? g_wq : ((cq == 1) ? g_wk : g_wv);
        float acc[4][4][4] = {};
        gemm_Ares_pass(As, Bs, W, acc, tid);

        const int prow = b * PQ + p0 + (wid & 1) * 64;
        if (cq == 0) {
            float* base = g_q + (size_t)prow * CQ + (wid >> 1) * 32;
#pragma unroll
            for (int mt = 0; mt < 4; mt++) {
                int r = mt * 16 + gid;
#pragma unroll
                for (int nt = 0; nt < 4; nt++) {
                    int c = nt * 8 + tig * 2;
                    *(float2*)(base + (size_t)r * CQ + c)       = make_float2(acc[mt][nt][0], acc[mt][nt][1]);
                    *(float2*)(base + (size_t)(r + 8) * CQ + c) = make_float2(acc[mt][nt][2], acc[mt][nt][3]);
                }
            }
        } else {
            uint32_t* base = g_kvh + (size_t)prow * 128 + (cq - 1) * 64 + (wid >> 1) * 16;
#pragma unroll
            for (int mt = 0; mt < 4; mt++) {
                int r = mt * 16 + gid;
#pragma unroll
                for (int nt = 0; nt < 4; nt++) {
                    int h2i = nt * 4 + tig;
                    __half2 lo = __floats2half2_rn(acc[mt][nt][0], acc[mt][nt][1]);
                    __half2 hi = __floats2half2_rn(acc[mt][nt][2], acc[mt][nt][3]);
                    base[(size_t)r * 128 + h2i]       = *(uint32_t*)&lo;
                    base[(size_t)(r + 8) * 128 + h2i] = *(uint32_t*)&hi;
                }
            }
        }
    }
}

// ---------------------------------------------------------------------------
// K3: attention + residual + BN (unchanged from round 11).
// ---------------------------------------------------------------------------
__global__ void __launch_bounds__(256) k_attn(const float* __restrict__ gamma,
                                              const float* __restrict__ beta,
                                              const float* __restrict__ mean,
                                              const float* __restrict__ var)
{
    __shared__ float s_scale[CQ], s_shift[CQ];
    int tid = threadIdx.x;
    if (tid < CQ) {
        float sc = gamma[tid] * rsqrtf(var[tid] + 1e-5f);
        s_scale[tid] = sc;
        s_shift[tid] = beta[tid] - mean[tid] * sc;
    }
    __syncthreads();

    int lane = tid & 31, w = tid >> 5;
    const float rs = 0.17677669529663687f; // 1/sqrt(32)

    for (int i = 0; i < 8; i++) {
        int g = blockIdx.x * 64 + w * 8 + i;
        int b = g >> 14;
        int bbase = b << 14;

        float4 qv = ((const float4*)(g_q + (size_t)g * CQ))[lane];

        const uint32_t* kvrow = g_kvh + (size_t)g * 128;
        uint2 su = *(const uint2*)(kvrow + 2 * lane);
        uint2 vu = *(const uint2*)(kvrow + 64 + 2 * lane);
        float2 k0 = __half22float2(*(__half2*)&su.x);
        float2 k1 = __half22float2(*(__half2*)&su.y);
        float2 v0 = __half22float2(*(__half2*)&vu.x);
        float2 v1 = __half22float2(*(__half2*)&vu.y);

        const int* irow = g_idx + (size_t)g * KQ;
        int myidx = irow[lane & 15];

        float dself;
        {
            float p = qv.x * k0.x + qv.y * k0.y + qv.z * k1.x + qv.w * k1.y;
            p += __shfl_xor_sync(0xffffffffu, p, 1);
            p += __shfl_xor_sync(0xffffffffu, p, 2);
            p += __shfl_xor_sync(0xffffffffu, p, 4);
            dself = p;
        }

        float e[16];
#pragma unroll
        for (int k = 0; k < 16; k++) {
            int nb = __shfl_sync(0xffffffffu, myidx, k);
            uint2 ku = *(const uint2*)(g_kvh + (size_t)(bbase + nb) * 128 + 2 * lane);
            float2 f0 = __half22float2(*(__half2*)&ku.x);
            float2 f1 = __half22float2(*(__half2*)&ku.y);
            float p = qv.x * f0.x + qv.y * f0.y + qv.z * f1.x + qv.w * f1.y;
            p += __shfl_xor_sync(0xffffffffu, p, 1);
            p += __shfl_xor_sync(0xffffffffu, p, 2);
            p += __shfl_xor_sync(0xffffffffu, p, 4);
            e[k] = (dself - p) * rs;
        }

        float mx = e[0];
#pragma unroll
        for (int k = 1; k < 16; k++) mx = fmaxf(mx, e[k]);
        float s = 0.f;
#pragma unroll
        for (int k = 0; k < 16; k++) { e[k] = __expf(e[k] - mx); s += e[k]; }
        float inv = 1.0f / s;

        float4 acc = make_float4(v0.x, v0.y, v1.x, v1.y);
#pragma unroll
        for (int k = 0; k < 16; k++) {
            int nb = __shfl_sync(0xffffffffu, myidx, k);
            uint2 wu = *(const uint2*)(g_kvh + (size_t)(bbase + nb) * 128 + 64 + 2 * lane);
            float2 f0 = __half22float2(*(__half2*)&wu.x);
            float2 f1 = __half22float2(*(__half2*)&wu.y);
            float a = e[k] * inv;
            acc.x -= a * f0.x; acc.y -= a * f0.y;
            acc.z -= a * f1.x; acc.w -= a * f1.y;
        }

        const float4* xp = (const float4*)(g_xpm + (size_t)g * CQ);
        float4 xv = xp[lane];
        int c = lane * 4;
        float4 hv;
        hv.x = f2tff((xv.x + acc.x) * s_scale[c + 0] + s_shift[c + 0]);
        hv.y = f2tff((xv.y + acc.y) * s_scale[c + 1] + s_shift[c + 1]);
        hv.z = f2tff((xv.z + acc.z) * s_scale[c + 2] + s_shift[c + 2]);
        hv.w = f2tff((xv.w + acc.w) * s_scale[c + 3] + s_shift[c + 3]);
        ((float4*)(g_h + (size_t)g * CQ))[lane] = hv;
    }
}

// K4: W1 with resident h tile; epilogue packs leaky output to half2. grid (PQ/128, B).
__global__ void __launch_bounds__(256) k_gemm_w1()
{
    extern __shared__ uint32_t sm[];
    uint32_t* As = sm;
    uint32_t* Bs = sm + 128 * 132;

    const int b = blockIdx.y;
    const int p0 = blockIdx.x * 128;
    const int tid = threadIdx.x;
    const float* A = g_h + (size_t)(b * PQ + p0) * CQ;

#pragma unroll
    for (int it = 0; it < 16; it++) {
        int id = tid + it * 256;
        int r = id >> 5, seg = (id & 31) * 4;
        cp16(&As[r * 132 + seg], A + (size_t)r * CQ + seg);
    }
    cp_commit();

    const int lane = tid & 31, wid = tid >> 5;
    const int gid = lane >> 2, tig = lane & 3;

#pragma unroll 1
    for (int nt4 = 0; nt4 < 4; nt4++) {
        const int co0 = nt4 * 128;
        float acc[4][4][4] = {};
        gemm_Ares_pass(As, Bs, g_w1 + (size_t)co0 * CQ, acc, tid);

        // half2-packed hid: row stride 256 u32; this warp covers u32 range
        // [co0/2 + (wid>>1)*16, +16)
        uint32_t* base = g_hidh + (size_t)(b * PQ + p0 + (wid & 1) * 64) * (HIDQ / 2)
                       + co0 / 2 + (wid >> 1) * 16;
#pragma unroll
        for (int mt = 0; mt < 4; mt++) {
            int r = mt * 16 + gid;
#pragma unroll
            for (int nt = 0; nt < 4; nt++) {
                int h2i = nt * 4 + tig;
                float v0 = acc[mt][nt][0], v1 = acc[mt][nt][1];
                float v2 = acc[mt][nt][2], v3 = acc[mt][nt][3];
                v0 = v0 > 0.f ? v0 : 0.2f * v0;
                v1 = v1 > 0.f ? v1 : 0.2f * v1;
                v2 = v2 > 0.f ? v2 : 0.2f * v2;
                v3 = v3 > 0.f ? v3 : 0.2f * v3;
                __half2 lo = __floats2half2_rn(v0, v1);
                __half2 hi = __floats2half2_rn(v2, v3);
                base[(size_t)r * (HIDQ / 2) + h2i]       = *(uint32_t*)&lo;
                base[(size_t)(r + 8) * (HIDQ / 2) + h2i] = *(uint32_t*)&hi;
            }
        }
    }
}

// ---------------------------------------------------------------------------
// K5: y = W2 @ hid with fp16 m16n8k16 MMA. Streaming core: KC = 32 halfs
// (16 u32) per chunk, 16 chunks, double-buffered, pad-20 rows.
// grid (PQ/128, 1, B).
// ---------------------------------------------------------------------------
__global__ void __launch_bounds__(256) k_gemm_w2(float* __restrict__ out)
{
    __shared__ uint32_t As[2][128 * 20];
    __shared__ uint32_t Bs[2][128 * 20];

    const int b = blockIdx.z;
    const int p0 = blockIdx.x * 128;
    const int tid = threadIdx.x;
    const uint32_t* Ag = g_hidh + (size_t)(b * PQ + p0) * (HIDQ / 2);

    const int lane = tid & 31, wid = tid >> 5;
    const int gid = lane >> 2, tig = lane & 3;
    const int mbase = (wid & 1) * 64, nbase = (wid >> 1) * 32;
    const int r0 = tid >> 2, s0 = (tid & 3) * 4;
    const int r1 = r0 + 64;

    float acc[4][4][4] = {};

    // prologue: chunk 0 (u32 k-index 0..15 per row)
    cp16(&As[0][r0 * 20 + s0], Ag + (size_t)r0 * (HIDQ / 2) + s0);
    cp16(&As[0][r1 * 20 + s0], Ag + (size_t)r1 * (HIDQ / 2) + s0);
    cp16(&Bs[0][r0 * 20 + s0], g_w2h + (size_t)r0 * (HIDQ / 2) + s0);
    cp16(&Bs[0][r1 * 20 + s0], g_w2h + (size_t)r1 * (HIDQ / 2) + s0);
    cp_commit();

#pragma unroll 1
    for (int kc = 0; kc < 16; kc++) {
        const int st = kc & 1;
        cp_wait<0>();
        __syncthreads();
        if (kc + 1 < 16) {
            const int k0g = (kc + 1) * 16;
            cp16(&As[st ^ 1][r0 * 20 + s0], Ag + (size_t)r0 * (HIDQ / 2) + k0g + s0);
            cp16(&As[st ^ 1][r1 * 20 + s0], Ag + (size_t)r1 * (HIDQ / 2) + k0g + s0);
            cp16(&Bs[st ^ 1][r0 * 20 + s0], g_w2h + (size_t)r0 * (HIDQ / 2) + k0g + s0);
            cp16(&Bs[st ^ 1][r1 * 20 + s0], g_w2h + (size_t)r1 * (HIDQ / 2) + k0g + s0);
            cp_commit();
        }

        // 2 k16-MMA steps per 32-half chunk (u32 bases 0 and 8)
#pragma unroll
        for (int ks = 0; ks < 2; ks++) {
            const int k0 = ks * 8;
            uint32_t af[4][4], bf[4][2];
#pragma unroll
            for (int mt = 0; mt < 4; mt++) {
                int m = mbase + mt * 16 + gid;
                af[mt][0] = As[st][m * 20 + k0 + tig];          // rows m,   k 2t..2t+1
                af[mt][1] = As[st][(m + 8) * 20 + k0 + tig];    // rows m+8
                af[mt][2] = As[st][m * 20 + k0 + 4 + tig];      // rows m,   k 8+2t
                af[mt][3] = As[st][(m + 8) * 20 + k0 + 4 + tig];
            }
#pragma unroll
            for (int nt = 0; nt < 4; nt++) {
                int n = nbase + nt * 8 + gid;
                bf[nt][0] = Bs[st][n * 20 + k0 + tig];          // col n, k 2t..2t+1
                bf[nt][1] = Bs[st][n * 20 + k0 + 4 + tig];      // col n, k 8+2t
            }
#pragma unroll
            for (int mt = 0; mt < 4; mt++)
#pragma unroll
                for (int nt = 0; nt < 4; nt++)
                    mma_f16(acc[mt][nt], af[mt][0], af[mt][1], af[mt][2], af[mt][3],
                            bf[nt][0], bf[nt][1]);
        }
    }

    float* ob = out + (size_t)b * OUTC * PQ + (size_t)4 * PQ;
    int rbase = p0 + mbase;
#pragma unroll
    for (int mt = 0; mt < 4; mt++) {
        int r = rbase + mt * 16 + gid;
#pragma unroll
        for (int nt = 0; nt < 4; nt++) {
            int c = nbase + nt * 8 + tig * 2;
            ob[(size_t)c * PQ + r]           = acc[mt][nt][0];
            ob[(size_t)(c + 1) * PQ + r]     = acc[mt][nt][1];
            ob[(size_t)c * PQ + r + 8]       = acc[mt][nt][2];
            ob[(size_t)(c + 1) * PQ + r + 8] = acc[mt][nt][3];
        }
    }
}

// ---------------------------------------------------------------------------
extern "C" void kernel_launch(void* const* d_in, const int* in_sizes, int n_in,
                              void* d_out, int out_size)
{
    const float* x     = (const float*)d_in[0];
    const float* Wq    = (const float*)d_in[1];
    const float* Wk    = (const float*)d_in[2];
    const float* Wv    = (const float*)d_in[3];
    const float* W1    = (const float*)d_in[4];
    const float* W2    = (const float*)d_in[5];
    const float* gamma = (const float*)d_in[6];
    const float* beta  = (const float*)d_in[7];
    const float* mean  = (const float*)d_in[8];
    const float* var   = (const float*)d_in[9];
    float* out = (float*)d_out;

    static cudaStream_t s2;
    static cudaEvent_t evFork, evJoin;
    static int init_done = 0;
    if (!init_done) {
        cudaFuncSetAttribute(k_gemm_qkv, cudaFuncAttributeMaxDynamicSharedMemorySize, ARES_SMEM);
        cudaFuncSetAttribute(k_gemm_w1,  cudaFuncAttributeMaxDynamicSharedMemorySize, ARES_SMEM);
        cudaStreamCreateWithFlags(&s2, cudaStreamNonBlocking);
        cudaEventCreateWithFlags(&evFork, cudaEventDisableTiming);
        cudaEventCreateWithFlags(&evJoin, cudaEventDisableTiming);
        init_done = 1;
    }

    // Round-8 structure: single fork for topk, everything else serial full-grid.
    cudaEventRecord(evFork, 0);
    cudaStreamWaitEvent(s2, evFork, 0);
    k_topk<<<dim3(TQ, BQ, 8), 256, 0, s2>>>(x);
    cudaEventRecord(evJoin, s2);

    k_roundw<<<256, 256>>>(Wq, Wk, Wv, W1, W2);
    k_transpose<<<dim3(PQ / 32, CQ / 32, BQ), dim3(32, 8)>>>(x, out);
    k_gemm_qkv<<<dim3(PQ / 128, BQ), 256, ARES_SMEM>>>();

    cudaStreamWaitEvent(0, evJoin, 0);
    k_attn<<<dim3((BQ * PQ) / 64, 1, 1), 256>>>(gamma, beta, mean, var);
    k_gemm_w1<<<dim3(PQ / 128, BQ), 256, ARES_SMEM>>>();
    k_gemm_w2<<<dim3(PQ / 128, 1, BQ), 256>>>(out);
}

// round 13
// speedup vs baseline: 1.3157x; 1.0369x over previous
#include <cuda_runtime.h>
#include <cuda_fp16.h>
#include <math.h>
#include <stdint.h>

// Problem constants
#define BQ 2
#define CQ 128
#define TQ 32
#define NQ 512
#define PQ (TQ * NQ)      // 16384 points per batch
#define KQ 16
#define HIDQ 512
#define OUTC 132
#define THREEN 1536

// ---------------------------------------------------------------------------
// Device scratch (static — no allocations allowed)
// ---------------------------------------------------------------------------
__device__ float    g_xpm[BQ * PQ * CQ];   // x transposed (b,p,c), full precision
__device__ float    g_xtf[BQ * PQ * CQ];   // x transposed, tf32-rounded
__device__ float    g_q[BQ * PQ * CQ];     // q projection, fp32, point-major
__device__ uint32_t g_kvh[BQ * PQ * 128];  // per point: [0..63] kx half2, [64..127] vx half2
__device__ int      g_idx[BQ * PQ * KQ];   // neighbor composite index t_eff*N + n'
__device__ uint32_t g_hh[BQ * PQ * 64];    // post-attn+BN h, half2 packed (W1 input)
__device__ uint32_t g_hidh[BQ * PQ * (HIDQ / 2)];  // leaky(W1@h), half2 packed (W2 input)
__device__ float    g_wq[CQ * CQ], g_wk[CQ * CQ], g_wv[CQ * CQ];
__device__ uint32_t g_w1h[(HIDQ * CQ) / 2];        // W1 half2 packed along k
__device__ uint32_t g_w2h[(CQ * HIDQ) / 2];        // W2 half2 packed along k

// ---------------------------------------------------------------------------
// tf32 / fp16 / async helpers
// ---------------------------------------------------------------------------
__device__ __forceinline__ uint32_t f2tf(float f)
{
    uint32_t r;
    asm("cvt.rna.tf32.f32 %0, %1;" : "=r"(r) : "f"(f));
    return r;
}
__device__ __forceinline__ float f2tff(float f) { return __uint_as_float(f2tf(f)); }

__device__ __forceinline__ void mma_tf32(float c[4],
                                         uint32_t a0, uint32_t a1, uint32_t a2, uint32_t a3,
                                         uint32_t b0, uint32_t b1)
{
    asm volatile(
        "mma.sync.aligned.m16n8k8.row.col.f32.tf32.tf32.f32 "
        "{%0,%1,%2,%3},{%4,%5,%6,%7},{%8,%9},{%0,%1,%2,%3};"
        : "+f"(c[0]), "+f"(c[1]), "+f"(c[2]), "+f"(c[3])
        : "r"(a0), "r"(a1), "r"(a2), "r"(a3), "r"(b0), "r"(b1));
}

__device__ __forceinline__ void mma_f16(float c[4],
                                        uint32_t a0, uint32_t a1, uint32_t a2, uint32_t a3,
                                        uint32_t b0, uint32_t b1)
{
    asm volatile(
        "mma.sync.aligned.m16n8k16.row.col.f32.f16.f16.f32 "
        "{%0,%1,%2,%3},{%4,%5,%6,%7},{%8,%9},{%0,%1,%2,%3};"
        : "+f"(c[0]), "+f"(c[1]), "+f"(c[2]), "+f"(c[3])
        : "r"(a0), "r"(a1), "r"(a2), "r"(a3), "r"(b0), "r"(b1));
}

__device__ __forceinline__ void cp16(uint32_t* dst_smem, const void* src)
{
    uint32_t d = (uint32_t)__cvta_generic_to_shared(dst_smem);
    asm volatile("cp.async.cg.shared.global [%0], [%1], 16;" :: "r"(d), "l"(src));
}
__device__ __forceinline__ void cp_commit() { asm volatile("cp.async.commit_group;" ::: "memory"); }
template<int N>
__device__ __forceinline__ void cp_wait() { asm volatile("cp.async.wait_group %0;" :: "n"(N) : "memory"); }

// ---------------------------------------------------------------------------
// K_pre: round weights (tf32 Wq/Wk/Wv; packed fp16 W1/W2).
// ---------------------------------------------------------------------------
__global__ void k_roundw(const float* __restrict__ Wq, const float* __restrict__ Wk,
                         const float* __restrict__ Wv, const float* __restrict__ W1,
                         const float* __restrict__ W2)
{
    int i = blockIdx.x * 256 + threadIdx.x;   // 0 .. 65535
    if (i < CQ * CQ) {
        g_wq[i] = f2tff(Wq[i]);
        g_wk[i] = f2tff(Wk[i]);
        g_wv[i] = f2tff(Wv[i]);
    }
    if (i < (HIDQ * CQ) / 2) {
        __half2 h1 = __floats2half2_rn(W1[2 * i], W1[2 * i + 1]);
        g_w1h[i] = *(uint32_t*)&h1;
        __half2 h2 = __floats2half2_rn(W2[2 * i], W2[2 * i + 1]);
        g_w2h[i] = *(uint32_t*)&h2;
    }
}

// ---------------------------------------------------------------------------
// K0: transpose x (B,C,P) -> g_xpm (full) and g_xtf (tf32-rounded), (B,P,C).
// Also writes out channels 0..3 directly.
// ---------------------------------------------------------------------------
__global__ void k_transpose(const float* __restrict__ x, float* __restrict__ out)
{
    __shared__ float tile[32][33];
    int b = blockIdx.z;
    int p0 = blockIdx.x * 32;
    int c0 = blockIdx.y * 32;
    const float* xb = x + (size_t)b * CQ * PQ;
    int tx = threadIdx.x, ty = threadIdx.y;
#pragma unroll
    for (int i = 0; i < 32; i += 8) {
        float v = xb[(size_t)(c0 + ty + i) * PQ + p0 + tx];
        tile[ty + i][tx] = v;
        if (c0 == 0 && (ty + i) < 4)
            out[(size_t)b * OUTC * PQ + (size_t)(ty + i) * PQ + p0 + tx] = v;
    }
    __syncthreads();
    float* op  = g_xpm + (size_t)b * PQ * CQ;
    float* op2 = g_xtf + (size_t)b * PQ * CQ;
#pragma unroll
    for (int i = 0; i < 32; i += 8) {
        float v = tile[tx][ty + i];
        size_t o = (size_t)(p0 + ty + i) * CQ + c0 + tx;
        op[o]  = v;
        op2[o] = f2tff(v);
    }
}

// ---------------------------------------------------------------------------
// K1: top-K neighbor selection (exact; unchanged).
// ---------------------------------------------------------------------------
__global__ void __launch_bounds__(256) k_topk(const float* __restrict__ x)
{
    int t = blockIdx.x, b = blockIdx.y, z = blockIdx.z;
    __shared__ float sc[3][THREEN];
    const float* xb = x + (size_t)b * CQ * PQ;
    int tid = threadIdx.x;

    for (int i = tid; i < 3 * THREEN; i += 256) {
        int c = i / THREEN, m = i % THREEN;
        int j = m >> 9, nn = m & 511;
        int te = t - 1 + j;
        te = te < 0 ? 0 : (te > TQ - 1 ? TQ - 1 : te);
        sc[c][m] = xb[(size_t)c * PQ + te * NQ + nn];
    }
    __syncthreads();

    const unsigned FULL = 0xffffffffu;
    const float FINF = __int_as_float(0x7f800000);
    int lane = tid & 31, w = tid >> 5;

    for (int i = 0; i < 8; i++) {
        int n = z * 64 + w * 8 + i;
        float a0 = sc[0][512 + n], a1 = sc[1][512 + n], a2 = sc[2][512 + n];

        float e0 = FINF, e1 = FINF, e2 = FINF, e3 = FINF;
        int   q0 = 0,    q1 = 0,    q2 = 0,    q3 = 0;
#pragma unroll
        for (int jj = 0; jj < 48; jj++) {
            int m = jj * 32 + lane;
            float dx = sc[0][m] - a0;
            float dy = sc[1][m] - a1;
            float dz = sc[2][m] - a2;
            float dc = dx * dx + dy * dy + dz * dz;
            bool l0 = dc < e0, l1 = dc < e1, l2 = dc < e2, l3 = dc < e3;
            e3 = l3 ? (l2 ? e2 : dc) : e3;  q3 = l3 ? (l2 ? q2 : m) : q3;
            e2 = l2 ? (l1 ? e1 : dc) : e2;  q2 = l2 ? (l1 ? q1 : m) : q2;
            e1 = l1 ? (l0 ? e0 : dc) : e1;  q1 = l1 ? (l0 ? q0 : m) : q1;
            e0 = l0 ? dc : e0;              q0 = l0 ? m : q0;
        }

        int ptr = 0;
        bool bad = false;
        int* orow = g_idx + ((size_t)(b * TQ + t) * NQ + n) * KQ;
#pragma unroll
        for (int it = 0; it < KQ; it++) {
            bad |= __any_sync(FULL, ptr >= 4);
            unsigned long long mykey =
                ((unsigned long long)__float_as_uint(e0) << 32) | (unsigned)q0;
            unsigned long long k = mykey;
#pragma unroll
            for (int off = 16; off; off >>= 1) {
                unsigned long long o = __shfl_xor_sync(FULL, k, off);
                if (o < k) k = o;
            }
            if (mykey == k) {
                e0 = e1; q0 = q1; e1 = e2; q1 = q2; e2 = e3; q2 = q3;
                e3 = FINF; q3 = 0; ptr++;
            }
            if (lane == 0) {
                int m = (int)(k & 0xffffffffu);
                int jwin = m >> 9, nwin = m & 511;
                int te = t - 1 + jwin;
                te = te < 0 ? 0 : (te > TQ - 1 ? TQ - 1 : te);
                orow[it] = te * NQ + nwin;
            }
        }

        if (bad) {
            unsigned long long removed = 0ull;
            for (int it = 0; it < KQ; it++) {
                float best = 3.4e38f;
                int bj = 0;
#pragma unroll
                for (int jj = 0; jj < 48; jj++) {
                    int m = jj * 32 + lane;
                    float dx = sc[0][m] - a0;
                    float dy = sc[1][m] - a1;
                    float dz = sc[2][m] - a2;
                    float dc = dx * dx + dy * dy + dz * dz;
                    bool alive = !(removed & (1ull << jj));
                    if (alive && dc < best) { best = dc; bj = jj; }
                }
                int bm = bj * 32 + lane;
#pragma unroll
                for (int off = 16; off; off >>= 1) {
                    float od = __shfl_xor_sync(FULL, best, off);
                    int   om = __shfl_xor_sync(FULL, bm, off);
                    if (od < best || (od == best && om < bm)) { best = od; bm = om; }
                }
                if ((bm & 31) == lane) removed |= (1ull << (bm >> 5));
                if (lane == 0) {
                    int jwin = bm >> 9, nwin = bm & 511;
                    int te = t - 1 + jwin;
                    te = te < 0 ? 0 : (te > TQ - 1 ? TQ - 1 : te);
                    orow[it] = te * NQ + nwin;
                }
            }
        }
    }
}

// ---------------------------------------------------------------------------
// A-resident tf32 GEMM compute (used by qkv).
// ---------------------------------------------------------------------------
__device__ __forceinline__ void gemm_Ares_pass(const uint32_t* __restrict__ As,
                                               uint32_t* __restrict__ Bs,
                                               const float* __restrict__ W,
                                               float acc[4][4][4],
                                               int tid)
{
    const int lane = tid & 31, wid = tid >> 5;
    const int gid = lane >> 2, tig = lane & 3;
    const int mbase = (wid & 1) * 64, nbase = (wid >> 1) * 32;
    const int r0 = tid >> 2, s0 = (tid & 3) * 4;
    const int r1 = r0 + 64;

    cp16(&Bs[r0 * 20 + s0], W + (size_t)r0 * CQ + s0);
    cp16(&Bs[r1 * 20 + s0], W + (size_t)r1 * CQ + s0);
    cp_commit();

#pragma unroll 1
    for (int kc = 0; kc < 8; kc++) {
        const int st = kc & 1;
        cp_wait<0>();
        __syncthreads();
        if (kc + 1 < 8) {
            const int k0g = (kc + 1) * 16;
            uint32_t* Bd = Bs + (st ^ 1) * (128 * 20);
            cp16(&Bd[r0 * 20 + s0], W + (size_t)r0 * CQ + k0g + s0);
            cp16(&Bd[r1 * 20 + s0], W + (size_t)r1 * CQ + k0g + s0);
            cp_commit();
        }
        const uint32_t* Bc = Bs + st * (128 * 20);

#pragma unroll
        for (int ks = 0; ks < 2; ks++) {
            const int ka = kc * 16 + ks * 8;
            const int kb = ks * 8;
            uint32_t af[4][4], bf[4][2];
#pragma unroll
            for (int mt = 0; mt < 4; mt++) {
                int m = mbase + mt * 16 + gid;
                af[mt][0] = As[m * 132 + ka + tig];
                af[mt][1] = As[(m + 8) * 132 + ka + tig];
                af[mt][2] = As[m * 132 + ka + 4 + tig];
                af[mt][3] = As[(m + 8) * 132 + ka + 4 + tig];
            }
#pragma unroll
            for (int nt = 0; nt < 4; nt++) {
                int n = nbase + nt * 8 + gid;
                bf[nt][0] = Bc[n * 20 + kb + tig];
                bf[nt][1] = Bc[n * 20 + kb + 4 + tig];
            }
#pragma unroll
            for (int mt = 0; mt < 4; mt++)
#pragma unroll
                for (int nt = 0; nt < 4; nt++)
                    mma_tf32(acc[mt][nt], af[mt][0], af[mt][1], af[mt][2], af[mt][3],
                             bf[nt][0], bf[nt][1]);
        }
    }
}

#define ARES_SMEM ((128 * 132 + 2 * 128 * 20) * 4)   // 88064 B

// K2: merged QKV projection (unchanged from round 12).
__global__ void __launch_bounds__(256) k_gemm_qkv()
{
    extern __shared__ uint32_t sm[];
    uint32_t* As = sm;                    // [128][132]
    uint32_t* Bs = sm + 128 * 132;        // [2][128][20]

    const int b = blockIdx.y;
    const int p0 = blockIdx.x * 128;
    const int tid = threadIdx.x;
    const float* A = g_xtf + (size_t)(b * PQ + p0) * CQ;

#pragma unroll
    for (int it = 0; it < 16; it++) {
        int id = tid + it * 256;
        int r = id >> 5, seg = (id & 31) * 4;
        cp16(&As[r * 132 + seg], A + (size_t)r * CQ + seg);
    }
    cp_commit();

    const int lane = tid & 31, wid = tid >> 5;
    const int gid = lane >> 2, tig = lane & 3;

#pragma unroll 1
    for (int cq = 0; cq < 3; cq++) {
        const float* W = (cq == 0) ? g_wq : ((cq == 1) ? g_wk : g_wv);
        float acc[4][4][4] = {};
        gemm_Ares_pass(As, Bs, W, acc, tid);

        const int prow = b * PQ + p0 + (wid & 1) * 64;
        if (cq == 0) {
            float* base = g_q + (size_t)prow * CQ + (wid >> 1) * 32;
#pragma unroll
            for (int mt = 0; mt < 4; mt++) {
                int r = mt * 16 + gid;
#pragma unroll
                for (int nt = 0; nt < 4; nt++) {
                    int c = nt * 8 + tig * 2;
                    *(float2*)(base + (size_t)r * CQ + c)       = make_float2(acc[mt][nt][0], acc[mt][nt][1]);
                    *(float2*)(base + (size_t)(r + 8) * CQ + c) = make_float2(acc[mt][nt][2], acc[mt][nt][3]);
                }
            }
        } else {
            uint32_t* base = g_kvh + (size_t)prow * 128 + (cq - 1) * 64 + (wid >> 1) * 16;
#pragma unroll
            for (int mt = 0; mt < 4; mt++) {
                int r = mt * 16 + gid;
#pragma unroll
                for (int nt = 0; nt < 4; nt++) {
                    int h2i = nt * 4 + tig;
                    __half2 lo = __floats2half2_rn(acc[mt][nt][0], acc[mt][nt][1]);
                    __half2 hi = __floats2half2_rn(acc[mt][nt][2], acc[mt][nt][3]);
                    base[(size_t)r * 128 + h2i]       = *(uint32_t*)&lo;
                    base[(size_t)(r + 8) * 128 + h2i] = *(uint32_t*)&hi;
                }
            }
        }
    }
}

// ---------------------------------------------------------------------------
// K3: attention + residual + BN. h written as packed half2 (W1 is fp16 now).
// ---------------------------------------------------------------------------
__global__ void __launch_bounds__(256) k_attn(const float* __restrict__ gamma,
                                              const float* __restrict__ beta,
                                              const float* __restrict__ mean,
                                              const float* __restrict__ var)
{
    __shared__ float s_scale[CQ], s_shift[CQ];
    int tid = threadIdx.x;
    if (tid < CQ) {
        float sc = gamma[tid] * rsqrtf(var[tid] + 1e-5f);
        s_scale[tid] = sc;
        s_shift[tid] = beta[tid] - mean[tid] * sc;
    }
    __syncthreads();

    int lane = tid & 31, w = tid >> 5;
    const float rs = 0.17677669529663687f; // 1/sqrt(32)

    for (int i = 0; i < 8; i++) {
        int g = blockIdx.x * 64 + w * 8 + i;
        int b = g >> 14;
        int bbase = b << 14;

        float4 qv = ((const float4*)(g_q + (size_t)g * CQ))[lane];

        const uint32_t* kvrow = g_kvh + (size_t)g * 128;
        uint2 su = *(const uint2*)(kvrow + 2 * lane);
        uint2 vu = *(const uint2*)(kvrow + 64 + 2 * lane);
        float2 k0 = __half22float2(*(__half2*)&su.x);
        float2 k1 = __half22float2(*(__half2*)&su.y);
        float2 v0 = __half22float2(*(__half2*)&vu.x);
        float2 v1 = __half22float2(*(__half2*)&vu.y);

        const int* irow = g_idx + (size_t)g * KQ;
        int myidx = irow[lane & 15];

        float dself;
        {
            float p = qv.x * k0.x + qv.y * k0.y + qv.z * k1.x + qv.w * k1.y;
            p += __shfl_xor_sync(0xffffffffu, p, 1);
            p += __shfl_xor_sync(0xffffffffu, p, 2);
            p += __shfl_xor_sync(0xffffffffu, p, 4);
            dself = p;
        }

        float e[16];
#pragma unroll
        for (int k = 0; k < 16; k++) {
            int nb = __shfl_sync(0xffffffffu, myidx, k);
            uint2 ku = *(const uint2*)(g_kvh + (size_t)(bbase + nb) * 128 + 2 * lane);
            float2 f0 = __half22float2(*(__half2*)&ku.x);
            float2 f1 = __half22float2(*(__half2*)&ku.y);
            float p = qv.x * f0.x + qv.y * f0.y + qv.z * f1.x + qv.w * f1.y;
            p += __shfl_xor_sync(0xffffffffu, p, 1);
            p += __shfl_xor_sync(0xffffffffu, p, 2);
            p += __shfl_xor_sync(0xffffffffu, p, 4);
            e[k] = (dself - p) * rs;
        }

        float mx = e[0];
#pragma unroll
        for (int k = 1; k < 16; k++) mx = fmaxf(mx, e[k]);
        float s = 0.f;
#pragma unroll
        for (int k = 0; k < 16; k++) { e[k] = __expf(e[k] - mx); s += e[k]; }
        float inv = 1.0f / s;

        float4 acc = make_float4(v0.x, v0.y, v1.x, v1.y);
#pragma unroll
        for (int k = 0; k < 16; k++) {
            int nb = __shfl_sync(0xffffffffu, myidx, k);
            uint2 wu = *(const uint2*)(g_kvh + (size_t)(bbase + nb) * 128 + 64 + 2 * lane);
            float2 f0 = __half22float2(*(__half2*)&wu.x);
            float2 f1 = __half22float2(*(__half2*)&wu.y);
            float a = e[k] * inv;
            acc.x -= a * f0.x; acc.y -= a * f0.y;
            acc.z -= a * f1.x; acc.w -= a * f1.y;
        }

        const float4* xp = (const float4*)(g_xpm + (size_t)g * CQ);
        float4 xv = xp[lane];
        int c = lane * 4;
        float h0 = (xv.x + acc.x) * s_scale[c + 0] + s_shift[c + 0];
        float h1 = (xv.y + acc.y) * s_scale[c + 1] + s_shift[c + 1];
        float h2 = (xv.z + acc.z) * s_scale[c + 2] + s_shift[c + 2];
        float h3 = (xv.w + acc.w) * s_scale[c + 3] + s_shift[c + 3];
        __half2 lo = __floats2half2_rn(h0, h1);
        __half2 hi = __floats2half2_rn(h2, h3);
        ((uint2*)(g_hh + (size_t)g * 64))[lane] = make_uint2(*(uint32_t*)&lo, *(uint32_t*)&hi);
    }
}

// ---------------------------------------------------------------------------
// K4: hid = leaky(W1 @ h), full fp16 m16n8k16. A tile (h, 128x64 u32, pad 68)
// resident in smem; 4 co-chunks of 128 stream W1h through pad-20 double buffer.
// K = 128 halfs = 64 u32 -> 4 chunks of 16 u32, 2 k16-steps each.
// grid (PQ/128, B).
// ---------------------------------------------------------------------------
#define W1_SMEM ((128 * 68 + 2 * 128 * 20) * 4)   // 55296 B

__global__ void __launch_bounds__(256) k_gemm_w1()
{
    extern __shared__ uint32_t sm[];
    uint32_t* Ah = sm;                    // [128][68]
    uint32_t* Bs = sm + 128 * 68;         // [2][128][20]

    const int b = blockIdx.y;
    const int p0 = blockIdx.x * 128;
    const int tid = threadIdx.x;
    const uint32_t* A = g_hh + (size_t)(b * PQ + p0) * 64;

    // resident A: 128 rows x 64 u32 = 2048 cp16 transfers, 8 per thread
#pragma unroll
    for (int it = 0; it < 8; it++) {
        int id = tid + it * 256;
        int r = id >> 4, seg = (id & 15) * 4;
        cp16(&Ah[r * 68 + seg], A + (size_t)r * 64 + seg);
    }
    cp_commit();

    const int lane = tid & 31, wid = tid >> 5;
    const int gid = lane >> 2, tig = lane & 3;
    const int mbase = (wid & 1) * 64, nbase = (wid >> 1) * 32;
    const int r0 = tid >> 2, s0 = (tid & 3) * 4;
    const int r1 = r0 + 64;

#pragma unroll 1
    for (int nt4 = 0; nt4 < 4; nt4++) {
        const int co0 = nt4 * 128;
        const uint32_t* Wg = g_w1h + (size_t)co0 * 64;
        float acc[4][4][4] = {};

        // prologue: chunk 0
        cp16(&Bs[r0 * 20 + s0], Wg + (size_t)r0 * 64 + s0);
        cp16(&Bs[r1 * 20 + s0], Wg + (size_t)r1 * 64 + s0);
        cp_commit();

#pragma unroll 1
        for (int kc = 0; kc < 4; kc++) {
            const int st = kc & 1;
            cp_wait<0>();
            __syncthreads();
            if (kc + 1 < 4) {
                const int k0g = (kc + 1) * 16;
                uint32_t* Bd = Bs + (st ^ 1) * (128 * 20);
                cp16(&Bd[r0 * 20 + s0], Wg + (size_t)r0 * 64 + k0g + s0);
                cp16(&Bd[r1 * 20 + s0], Wg + (size_t)r1 * 64 + k0g + s0);
                cp_commit();
            }
            const uint32_t* Bc = Bs + st * (128 * 20);

#pragma unroll
            for (int ks = 0; ks < 2; ks++) {
                const int ka = kc * 16 + ks * 8;
                const int kb = ks * 8;
                uint32_t af[4][4], bf[4][2];
#pragma unroll
                for (int mt = 0; mt < 4; mt++) {
                    int m = mbase + mt * 16 + gid;
                    af[mt][0] = Ah[m * 68 + ka + tig];
                    af[mt][1] = Ah[(m + 8) * 68 + ka + tig];
                    af[mt][2] = Ah[m * 68 + ka + 4 + tig];
                    af[mt][3] = Ah[(m + 8) * 68 + ka + 4 + tig];
                }
#pragma unroll
                for (int nt = 0; nt < 4; nt++) {
                    int n = nbase + nt * 8 + gid;
                    bf[nt][0] = Bc[n * 20 + kb + tig];
                    bf[nt][1] = Bc[n * 20 + kb + 4 + tig];
                }
#pragma unroll
                for (int mt = 0; mt < 4; mt++)
#pragma unroll
                    for (int nt = 0; nt < 4; nt++)
                        mma_f16(acc[mt][nt], af[mt][0], af[mt][1], af[mt][2], af[mt][3],
                                bf[nt][0], bf[nt][1]);
            }
        }

        uint32_t* base = g_hidh + (size_t)(b * PQ + p0 + mbase) * (HIDQ / 2)
                       + co0 / 2 + (wid >> 1) * 16;
#pragma unroll
        for (int mt = 0; mt < 4; mt++) {
            int r = mt * 16 + gid;
#pragma unroll
            for (int nt = 0; nt < 4; nt++) {
                int h2i = nt * 4 + tig;
                float v0 = acc[mt][nt][0], v1 = acc[mt][nt][1];
                float v2 = acc[mt][nt][2], v3 = acc[mt][nt][3];
                v0 = v0 > 0.f ? v0 : 0.2f * v0;
                v1 = v1 > 0.f ? v1 : 0.2f * v1;
                v2 = v2 > 0.f ? v2 : 0.2f * v2;
                v3 = v3 > 0.f ? v3 : 0.2f * v3;
                __half2 lo = __floats2half2_rn(v0, v1);
                __half2 hi = __floats2half2_rn(v2, v3);
                base[(size_t)r * (HIDQ / 2) + h2i]       = *(uint32_t*)&lo;
                base[(size_t)(r + 8) * (HIDQ / 2) + h2i] = *(uint32_t*)&hi;
            }
        }
    }
}

// ---------------------------------------------------------------------------
// K5: y = W2 @ hid, fp16 m16n8k16 streaming (unchanged from round 12).
// ---------------------------------------------------------------------------
__global__ void __launch_bounds__(256) k_gemm_w2(float* __restrict__ out)
{
    __shared__ uint32_t As[2][128 * 20];
    __shared__ uint32_t Bs[2][128 * 20];

    const int b = blockIdx.z;
    const int p0 = blockIdx.x * 128;
    const int tid = threadIdx.x;
    const uint32_t* Ag = g_hidh + (size_t)(b * PQ + p0) * (HIDQ / 2);

    const int lane = tid & 31, wid = tid >> 5;
    const int gid = lane >> 2, tig = lane & 3;
    const int mbase = (wid & 1) * 64, nbase = (wid >> 1) * 32;
    const int r0 = tid >> 2, s0 = (tid & 3) * 4;
    const int r1 = r0 + 64;

    float acc[4][4][4] = {};

    cp16(&As[0][r0 * 20 + s0], Ag + (size_t)r0 * (HIDQ / 2) + s0);
    cp16(&As[0][r1 * 20 + s0], Ag + (size_t)r1 * (HIDQ / 2) + s0);
    cp16(&Bs[0][r0 * 20 + s0], g_w2h + (size_t)r0 * (HIDQ / 2) + s0);
    cp16(&Bs[0][r1 * 20 + s0], g_w2h + (size_t)r1 * (HIDQ / 2) + s0);
    cp_commit();

#pragma unroll 1
    for (int kc = 0; kc < 16; kc++) {
        const int st = kc & 1;
        cp_wait<0>();
        __syncthreads();
        if (kc + 1 < 16) {
            const int k0g = (kc + 1) * 16;
            cp16(&As[st ^ 1][r0 * 20 + s0], Ag + (size_t)r0 * (HIDQ / 2) + k0g + s0);
            cp16(&As[st ^ 1][r1 * 20 + s0], Ag + (size_t)r1 * (HIDQ / 2) + k0g + s0);
            cp16(&Bs[st ^ 1][r0 * 20 + s0], g_w2h + (size_t)r0 * (HIDQ / 2) + k0g + s0);
            cp16(&Bs[st ^ 1][r1 * 20 + s0], g_w2h + (size_t)r1 * (HIDQ / 2) + k0g + s0);
            cp_commit();
        }

#pragma unroll
        for (int ks = 0; ks < 2; ks++) {
            const int k0 = ks * 8;
            uint32_t af[4][4], bf[4][2];
#pragma unroll
            for (int mt = 0; mt < 4; mt++) {
                int m = mbase + mt * 16 + gid;
                af[mt][0] = As[st][m * 20 + k0 + tig];
                af[mt][1] = As[st][(m + 8) * 20 + k0 + tig];
                af[mt][2] = As[st][m * 20 + k0 + 4 + tig];
                af[mt][3] = As[st][(m + 8) * 20 + k0 + 4 + tig];
            }
#pragma unroll
            for (int nt = 0; nt < 4; nt++) {
                int n = nbase + nt * 8 + gid;
                bf[nt][0] = Bs[st][n * 20 + k0 + tig];
                bf[nt][1] = Bs[st][n * 20 + k0 + 4 + tig];
            }
#pragma unroll
            for (int mt = 0; mt < 4; mt++)
#pragma unroll
                for (int nt = 0; nt < 4; nt++)
                    mma_f16(acc[mt][nt], af[mt][0], af[mt][1], af[mt][2], af[mt][3],
                            bf[nt][0], bf[nt][1]);
        }
    }

    float* ob = out + (size_t)b * OUTC * PQ + (size_t)4 * PQ;
    int rbase = p0 + mbase;
#pragma unroll
    for (int mt = 0; mt < 4; mt++) {
        int r = rbase + mt * 16 + gid;
#pragma unroll
        for (int nt = 0; nt < 4; nt++) {
            int c = nbase + nt * 8 + tig * 2;
            ob[(size_t)c * PQ + r]           = acc[mt][nt][0];
            ob[(size_t)(c + 1) * PQ + r]     = acc[mt][nt][1];
            ob[(size_t)c * PQ + r + 8]       = acc[mt][nt][2];
            ob[(size_t)(c + 1) * PQ + r + 8] = acc[mt][nt][3];
        }
    }
}

// ---------------------------------------------------------------------------
extern "C" void kernel_launch(void* const* d_in, const int* in_sizes, int n_in,
                              void* d_out, int out_size)
{
    const float* x     = (const float*)d_in[0];
    const float* Wq    = (const float*)d_in[1];
    const float* Wk    = (const float*)d_in[2];
    const float* Wv    = (const float*)d_in[3];
    const float* W1    = (const float*)d_in[4];
    const float* W2    = (const float*)d_in[5];
    const float* gamma = (const float*)d_in[6];
    const float* beta  = (const float*)d_in[7];
    const float* mean  = (const float*)d_in[8];
    const float* var   = (const float*)d_in[9];
    float* out = (float*)d_out;

    static cudaStream_t s2;
    static cudaEvent_t evFork, evJoin;
    static int init_done = 0;
    if (!init_done) {
        cudaFuncSetAttribute(k_gemm_qkv, cudaFuncAttributeMaxDynamicSharedMemorySize, ARES_SMEM);
        cudaFuncSetAttribute(k_gemm_w1,  cudaFuncAttributeMaxDynamicSharedMemorySize, W1_SMEM);
        cudaStreamCreateWithFlags(&s2, cudaStreamNonBlocking);
        cudaEventCreateWithFlags(&evFork, cudaEventDisableTiming);
        cudaEventCreateWithFlags(&evJoin, cudaEventDisableTiming);
        init_done = 1;
    }

    // Round-8 structure: single fork for topk, everything else serial full-grid.
    cudaEventRecord(evFork, 0);
    cudaStreamWaitEvent(s2, evFork, 0);
    k_topk<<<dim3(TQ, BQ, 8), 256, 0, s2>>>(x);
    cudaEventRecord(evJoin, s2);

    k_roundw<<<256, 256>>>(Wq, Wk, Wv, W1, W2);
    k_transpose<<<dim3(PQ / 32, CQ / 32, BQ), dim3(32, 8)>>>(x, out);
    k_gemm_qkv<<<dim3(PQ / 128, BQ), 256, ARES_SMEM>>>();

    cudaStreamWaitEvent(0, evJoin, 0);
    k_attn<<<dim3((BQ * PQ) / 64, 1, 1), 256>>>(gamma, beta, mean, var);
    k_gemm_w1<<<dim3(PQ / 128, BQ), 256, W1_SMEM>>>();
    k_gemm_w2<<<dim3(PQ / 128, 1, BQ), 256>>>(out);
}

// round 14
// speedup vs baseline: 1.3173x; 1.0012x over previous
#include <cuda_runtime.h>
#include <cuda_fp16.h>
#include <math.h>
#include <stdint.h>

// Problem constants
#define BQ 2
#define CQ 128
#define TQ 32
#define NQ 512
#define PQ (TQ * NQ)      // 16384 points per batch
#define KQ 16
#define HIDQ 512
#define OUTC 132
#define THREEN 1536

// ---------------------------------------------------------------------------
// Device scratch (static — no allocations allowed)
// ---------------------------------------------------------------------------
__device__ float    g_xpm[BQ * PQ * CQ];   // x transposed (b,p,c), full precision (residual)
__device__ uint32_t g_xh[BQ * PQ * 64];    // x transposed, half2 packed (QKV input)
__device__ float    g_q[BQ * PQ * CQ];     // q projection, fp32, point-major
__device__ uint32_t g_kvh[BQ * PQ * 128];  // per point: [0..63] kx half2, [64..127] vx half2
__device__ int      g_idx[BQ * PQ * KQ];   // neighbor composite index t_eff*N + n'
__device__ uint32_t g_hh[BQ * PQ * 64];    // post-attn+BN h, half2 packed (W1 input)
__device__ uint32_t g_hidh[BQ * PQ * (HIDQ / 2)];  // leaky(W1@h), half2 packed (W2 input)
__device__ uint32_t g_wqh[(CQ * CQ) / 2];  // Wq half2 packed along k
__device__ uint32_t g_wkh[(CQ * CQ) / 2];  // Wk
__device__ uint32_t g_wvh[(CQ * CQ) / 2];  // Wv
__device__ uint32_t g_w1h[(HIDQ * CQ) / 2];
__device__ uint32_t g_w2h[(CQ * HIDQ) / 2];

// ---------------------------------------------------------------------------
// fp16 / async helpers
// ---------------------------------------------------------------------------
__device__ __forceinline__ void mma_f16(float c[4],
                                        uint32_t a0, uint32_t a1, uint32_t a2, uint32_t a3,
                                        uint32_t b0, uint32_t b1)
{
    asm volatile(
        "mma.sync.aligned.m16n8k16.row.col.f32.f16.f16.f32 "
        "{%0,%1,%2,%3},{%4,%5,%6,%7},{%8,%9},{%0,%1,%2,%3};"
        : "+f"(c[0]), "+f"(c[1]), "+f"(c[2]), "+f"(c[3])
        : "r"(a0), "r"(a1), "r"(a2), "r"(a3), "r"(b0), "r"(b1));
}

__device__ __forceinline__ void cp16(uint32_t* dst_smem, const void* src)
{
    uint32_t d = (uint32_t)__cvta_generic_to_shared(dst_smem);
    asm volatile("cp.async.cg.shared.global [%0], [%1], 16;" :: "r"(d), "l"(src));
}
__device__ __forceinline__ void cp_commit() { asm volatile("cp.async.commit_group;" ::: "memory"); }
template<int N>
__device__ __forceinline__ void cp_wait() { asm volatile("cp.async.wait_group %0;" :: "n"(N) : "memory"); }

// ---------------------------------------------------------------------------
// K_pre: pack all weights to half2.
// ---------------------------------------------------------------------------
__global__ void k_roundw(const float* __restrict__ Wq, const float* __restrict__ Wk,
                         const float* __restrict__ Wv, const float* __restrict__ W1,
                         const float* __restrict__ W2)
{
    int i = blockIdx.x * 256 + threadIdx.x;   // 0 .. 65535
    if (i < (CQ * CQ) / 2) {
        __half2 hq = __floats2half2_rn(Wq[2 * i], Wq[2 * i + 1]);
        __half2 hk = __floats2half2_rn(Wk[2 * i], Wk[2 * i + 1]);
        __half2 hv = __floats2half2_rn(Wv[2 * i], Wv[2 * i + 1]);
        g_wqh[i] = *(uint32_t*)&hq;
        g_wkh[i] = *(uint32_t*)&hk;
        g_wvh[i] = *(uint32_t*)&hv;
    }
    if (i < (HIDQ * CQ) / 2) {
        __half2 h1 = __floats2half2_rn(W1[2 * i], W1[2 * i + 1]);
        g_w1h[i] = *(uint32_t*)&h1;
        __half2 h2 = __floats2half2_rn(W2[2 * i], W2[2 * i + 1]);
        g_w2h[i] = *(uint32_t*)&h2;
    }
}

// ---------------------------------------------------------------------------
// K0: transpose x (B,C,P) -> g_xpm (fp32) and g_xh (half2 packed), (B,P,C).
// Also writes out channels 0..3 directly.
// ---------------------------------------------------------------------------
__global__ void k_transpose(const float* __restrict__ x, float* __restrict__ out)
{
    __shared__ float tile[32][33];
    int b = blockIdx.z;
    int p0 = blockIdx.x * 32;
    int c0 = blockIdx.y * 32;
    const float* xb = x + (size_t)b * CQ * PQ;
    int tx = threadIdx.x, ty = threadIdx.y;
#pragma unroll
    for (int i = 0; i < 32; i += 8) {
        float v = xb[(size_t)(c0 + ty + i) * PQ + p0 + tx];
        tile[ty + i][tx] = v;
        if (c0 == 0 && (ty + i) < 4)
            out[(size_t)b * OUTC * PQ + (size_t)(ty + i) * PQ + p0 + tx] = v;
    }
    __syncthreads();
    float* op = g_xpm + (size_t)b * PQ * CQ;
#pragma unroll
    for (int i = 0; i < 32; i += 8) {
        int p = p0 + ty + i;
        op[(size_t)p * CQ + c0 + tx] = tile[tx][ty + i];
        if (tx < 16) {
            __half2 h = __floats2half2_rn(tile[2 * tx][ty + i], tile[2 * tx + 1][ty + i]);
            g_xh[(size_t)(b * PQ + p) * 64 + c0 / 2 + tx] = *(uint32_t*)&h;
        }
    }
}

// ---------------------------------------------------------------------------
// K1: top-K neighbor selection (exact; unchanged).
// ---------------------------------------------------------------------------
__global__ void __launch_bounds__(256) k_topk(const float* __restrict__ x)
{
    int t = blockIdx.x, b = blockIdx.y, z = blockIdx.z;
    __shared__ float sc[3][THREEN];
    const float* xb = x + (size_t)b * CQ * PQ;
    int tid = threadIdx.x;

    for (int i = tid; i < 3 * THREEN; i += 256) {
        int c = i / THREEN, m = i % THREEN;
        int j = m >> 9, nn = m & 511;
        int te = t - 1 + j;
        te = te < 0 ? 0 : (te > TQ - 1 ? TQ - 1 : te);
        sc[c][m] = xb[(size_t)c * PQ + te * NQ + nn];
    }
    __syncthreads();

    const unsigned FULL = 0xffffffffu;
    const float FINF = __int_as_float(0x7f800000);
    int lane = tid & 31, w = tid >> 5;

    for (int i = 0; i < 8; i++) {
        int n = z * 64 + w * 8 + i;
        float a0 = sc[0][512 + n], a1 = sc[1][512 + n], a2 = sc[2][512 + n];

        float e0 = FINF, e1 = FINF, e2 = FINF, e3 = FINF;
        int   q0 = 0,    q1 = 0,    q2 = 0,    q3 = 0;
#pragma unroll
        for (int jj = 0; jj < 48; jj++) {
            int m = jj * 32 + lane;
            float dx = sc[0][m] - a0;
            float dy = sc[1][m] - a1;
            float dz = sc[2][m] - a2;
            float dc = dx * dx + dy * dy + dz * dz;
            bool l0 = dc < e0, l1 = dc < e1, l2 = dc < e2, l3 = dc < e3;
            e3 = l3 ? (l2 ? e2 : dc) : e3;  q3 = l3 ? (l2 ? q2 : m) : q3;
            e2 = l2 ? (l1 ? e1 : dc) : e2;  q2 = l2 ? (l1 ? q1 : m) : q2;
            e1 = l1 ? (l0 ? e0 : dc) : e1;  q1 = l1 ? (l0 ? q0 : m) : q1;
            e0 = l0 ? dc : e0;              q0 = l0 ? m : q0;
        }

        int ptr = 0;
        bool bad = false;
        int* orow = g_idx + ((size_t)(b * TQ + t) * NQ + n) * KQ;
#pragma unroll
        for (int it = 0; it < KQ; it++) {
            bad |= __any_sync(FULL, ptr >= 4);
            unsigned long long mykey =
                ((unsigned long long)__float_as_uint(e0) << 32) | (unsigned)q0;
            unsigned long long k = mykey;
#pragma unroll
            for (int off = 16; off; off >>= 1) {
                unsigned long long o = __shfl_xor_sync(FULL, k, off);
                if (o < k) k = o;
            }
            if (mykey == k) {
                e0 = e1; q0 = q1; e1 = e2; q1 = q2; e2 = e3; q2 = q3;
                e3 = FINF; q3 = 0; ptr++;
            }
            if (lane == 0) {
                int m = (int)(k & 0xffffffffu);
                int jwin = m >> 9, nwin = m & 511;
                int te = t - 1 + jwin;
                te = te < 0 ? 0 : (te > TQ - 1 ? TQ - 1 : te);
                orow[it] = te * NQ + nwin;
            }
        }

        if (bad) {
            unsigned long long removed = 0ull;
            for (int it = 0; it < KQ; it++) {
                float best = 3.4e38f;
                int bj = 0;
#pragma unroll
                for (int jj = 0; jj < 48; jj++) {
                    int m = jj * 32 + lane;
                    float dx = sc[0][m] - a0;
                    float dy = sc[1][m] - a1;
                    float dz = sc[2][m] - a2;
                    float dc = dx * dx + dy * dy + dz * dz;
                    bool alive = !(removed & (1ull << jj));
                    if (alive && dc < best) { best = dc; bj = jj; }
                }
                int bm = bj * 32 + lane;
#pragma unroll
                for (int off = 16; off; off >>= 1) {
                    float od = __shfl_xor_sync(FULL, best, off);
                    int   om = __shfl_xor_sync(FULL, bm, off);
                    if (od < best || (od == best && om < bm)) { best = od; bm = om; }
                }
                if ((bm & 31) == lane) removed |= (1ull << (bm >> 5));
                if (lane == 0) {
                    int jwin = bm >> 9, nwin = bm & 511;
                    int te = t - 1 + jwin;
                    te = te < 0 ? 0 : (te > TQ - 1 ? TQ - 1 : te);
                    orow[it] = te * NQ + nwin;
                }
            }
        }
    }
}

// ---------------------------------------------------------------------------
// Shared fp16 A-resident GEMM pass: A (128 x 64 u32, pad 68) resident,
// W (128 rows x 64 u32) streamed via pad-20 double buffer.
// K = 128 halfs = 64 u32 -> 4 chunks of 16 u32, 2 k16-steps each.
// ---------------------------------------------------------------------------
__device__ __forceinline__ void gemm_f16_Ares_pass(const uint32_t* __restrict__ Ah,
                                                   uint32_t* __restrict__ Bs,
                                                   const uint32_t* __restrict__ Wg,
                                                   float acc[4][4][4], int tid)
{
    const int lane = tid & 31, wid = tid >> 5;
    const int gid = lane >> 2, tig = lane & 3;
    const int mbase = (wid & 1) * 64, nbase = (wid >> 1) * 32;
    const int r0 = tid >> 2, s0 = (tid & 3) * 4;
    const int r1 = r0 + 64;

    cp16(&Bs[r0 * 20 + s0], Wg + (size_t)r0 * 64 + s0);
    cp16(&Bs[r1 * 20 + s0], Wg + (size_t)r1 * 64 + s0);
    cp_commit();

#pragma unroll 1
    for (int kc = 0; kc < 4; kc++) {
        const int st = kc & 1;
        cp_wait<0>();
        __syncthreads();
        if (kc + 1 < 4) {
            const int k0g = (kc + 1) * 16;
            uint32_t* Bd = Bs + (st ^ 1) * (128 * 20);
            cp16(&Bd[r0 * 20 + s0], Wg + (size_t)r0 * 64 + k0g + s0);
            cp16(&Bd[r1 * 20 + s0], Wg + (size_t)r1 * 64 + k0g + s0);
            cp_commit();
        }
        const uint32_t* Bc = Bs + st * (128 * 20);

#pragma unroll
        for (int ks = 0; ks < 2; ks++) {
            const int ka = kc * 16 + ks * 8;
            const int kb = ks * 8;
            uint32_t af[4][4], bf[4][2];
#pragma unroll
            for (int mt = 0; mt < 4; mt++) {
                int m = mbase + mt * 16 + gid;
                af[mt][0] = Ah[m * 68 + ka + tig];
                af[mt][1] = Ah[(m + 8) * 68 + ka + tig];
                af[mt][2] = Ah[m * 68 + ka + 4 + tig];
                af[mt][3] = Ah[(m + 8) * 68 + ka + 4 + tig];
            }
#pragma unroll
            for (int nt = 0; nt < 4; nt++) {
                int n = nbase + nt * 8 + gid;
                bf[nt][0] = Bc[n * 20 + kb + tig];
                bf[nt][1] = Bc[n * 20 + kb + 4 + tig];
            }
#pragma unroll
            for (int mt = 0; mt < 4; mt++)
#pragma unroll
                for (int nt = 0; nt < 4; nt++)
                    mma_f16(acc[mt][nt], af[mt][0], af[mt][1], af[mt][2], af[mt][3],
                            bf[nt][0], bf[nt][1]);
        }
    }
}

#define F16_ARES_SMEM ((128 * 68 + 2 * 128 * 20) * 4)   // 55296 B

// K2: merged QKV projection, full fp16. grid (PQ/128, B). A tile loaded once,
// 3 weight passes. q -> fp32 g_q; kx/vx -> g_kvh half2.
__global__ void __launch_bounds__(256) k_gemm_qkv()
{
    extern __shared__ uint32_t sm[];
    uint32_t* Ah = sm;                    // [128][68]
    uint32_t* Bs = sm + 128 * 68;         // [2][128][20]

    const int b = blockIdx.y;
    const int p0 = blockIdx.x * 128;
    const int tid = threadIdx.x;
    const uint32_t* A = g_xh + (size_t)(b * PQ + p0) * 64;

#pragma unroll
    for (int it = 0; it < 8; it++) {
        int id = tid + it * 256;
        int r = id >> 4, seg = (id & 15) * 4;
        cp16(&Ah[r * 68 + seg], A + (size_t)r * 64 + seg);
    }
    cp_commit();

    const int lane = tid & 31, wid = tid >> 5;
    const int gid = lane >> 2, tig = lane & 3;

#pragma unroll 1
    for (int cq = 0; cq < 3; cq++) {
        const uint32_t* Wg = (cq == 0) ? g_wqh : ((cq == 1) ? g_wkh : g_wvh);
        float acc[4][4][4] = {};
        gemm_f16_Ares_pass(Ah, Bs, Wg, acc, tid);

        const int prow = b * PQ + p0 + (wid & 1) * 64;
        if (cq == 0) {
            float* base = g_q + (size_t)prow * CQ + (wid >> 1) * 32;
#pragma unroll
            for (int mt = 0; mt < 4; mt++) {
                int r = mt * 16 + gid;
#pragma unroll
                for (int nt = 0; nt < 4; nt++) {
                    int c = nt * 8 + tig * 2;
                    *(float2*)(base + (size_t)r * CQ + c)       = make_float2(acc[mt][nt][0], acc[mt][nt][1]);
                    *(float2*)(base + (size_t)(r + 8) * CQ + c) = make_float2(acc[mt][nt][2], acc[mt][nt][3]);
                }
            }
        } else {
            uint32_t* base = g_kvh + (size_t)prow * 128 + (cq - 1) * 64 + (wid >> 1) * 16;
#pragma unroll
            for (int mt = 0; mt < 4; mt++) {
                int r = mt * 16 + gid;
#pragma unroll
                for (int nt = 0; nt < 4; nt++) {
                    int h2i = nt * 4 + tig;
                    __half2 lo = __floats2half2_rn(acc[mt][nt][0], acc[mt][nt][1]);
                    __half2 hi = __floats2half2_rn(acc[mt][nt][2], acc[mt][nt][3]);
                    base[(size_t)r * 128 + h2i]       = *(uint32_t*)&lo;
                    base[(size_t)(r + 8) * 128 + h2i] = *(uint32_t*)&hi;
                }
            }
        }
    }
}

// ---------------------------------------------------------------------------
// K3: attention + residual + BN (unchanged from round 13).
// ---------------------------------------------------------------------------
__global__ void __launch_bounds__(256) k_attn(const float* __restrict__ gamma,
                                              const float* __restrict__ beta,
                                              const float* __restrict__ mean,
                                              const float* __restrict__ var)
{
    __shared__ float s_scale[CQ], s_shift[CQ];
    int tid = threadIdx.x;
    if (tid < CQ) {
        float sc = gamma[tid] * rsqrtf(var[tid] + 1e-5f);
        s_scale[tid] = sc;
        s_shift[tid] = beta[tid] - mean[tid] * sc;
    }
    __syncthreads();

    int lane = tid & 31, w = tid >> 5;
    const float rs = 0.17677669529663687f; // 1/sqrt(32)

    for (int i = 0; i < 8; i++) {
        int g = blockIdx.x * 64 + w * 8 + i;
        int b = g >> 14;
        int bbase = b << 14;

        float4 qv = ((const float4*)(g_q + (size_t)g * CQ))[lane];

        const uint32_t* kvrow = g_kvh + (size_t)g * 128;
        uint2 su = *(const uint2*)(kvrow + 2 * lane);
        uint2 vu = *(const uint2*)(kvrow + 64 + 2 * lane);
        float2 k0 = __half22float2(*(__half2*)&su.x);
        float2 k1 = __half22float2(*(__half2*)&su.y);
        float2 v0 = __half22float2(*(__half2*)&vu.x);
        float2 v1 = __half22float2(*(__half2*)&vu.y);

        const int* irow = g_idx + (size_t)g * KQ;
        int myidx = irow[lane & 15];

        float dself;
        {
            float p = qv.x * k0.x + qv.y * k0.y + qv.z * k1.x + qv.w * k1.y;
            p += __shfl_xor_sync(0xffffffffu, p, 1);
            p += __shfl_xor_sync(0xffffffffu, p, 2);
            p += __shfl_xor_sync(0xffffffffu, p, 4);
            dself = p;
        }

        float e[16];
#pragma unroll
        for (int k = 0; k < 16; k++) {
            int nb = __shfl_sync(0xffffffffu, myidx, k);
            uint2 ku = *(const uint2*)(g_kvh + (size_t)(bbase + nb) * 128 + 2 * lane);
            float2 f0 = __half22float2(*(__half2*)&ku.x);
            float2 f1 = __half22float2(*(__half2*)&ku.y);
            float p = qv.x * f0.x + qv.y * f0.y + qv.z * f1.x + qv.w * f1.y;
            p += __shfl_xor_sync(0xffffffffu, p, 1);
            p += __shfl_xor_sync(0xffffffffu, p, 2);
            p += __shfl_xor_sync(0xffffffffu, p, 4);
            e[k] = (dself - p) * rs;
        }

        float mx = e[0];
#pragma unroll
        for (int k = 1; k < 16; k++) mx = fmaxf(mx, e[k]);
        float s = 0.f;
#pragma unroll
        for (int k = 0; k < 16; k++) { e[k] = __expf(e[k] - mx); s += e[k]; }
        float inv = 1.0f / s;

        float4 acc = make_float4(v0.x, v0.y, v1.x, v1.y);
#pragma unroll
        for (int k = 0; k < 16; k++) {
            int nb = __shfl_sync(0xffffffffu, myidx, k);
            uint2 wu = *(const uint2*)(g_kvh + (size_t)(bbase + nb) * 128 + 64 + 2 * lane);
            float2 f0 = __half22float2(*(__half2*)&wu.x);
            float2 f1 = __half22float2(*(__half2*)&wu.y);
            float a = e[k] * inv;
            acc.x -= a * f0.x; acc.y -= a * f0.y;
            acc.z -= a * f1.x; acc.w -= a * f1.y;
        }

        const float4* xp = (const float4*)(g_xpm + (size_t)g * CQ);
        float4 xv = xp[lane];
        int c = lane * 4;
        float h0 = (xv.x + acc.x) * s_scale[c + 0] + s_shift[c + 0];
        float h1 = (xv.y + acc.y) * s_scale[c + 1] + s_shift[c + 1];
        float h2 = (xv.z + acc.z) * s_scale[c + 2] + s_shift[c + 2];
        float h3 = (xv.w + acc.w) * s_scale[c + 3] + s_shift[c + 3];
        __half2 lo = __floats2half2_rn(h0, h1);
        __half2 hi = __floats2half2_rn(h2, h3);
        ((uint2*)(g_hh + (size_t)g * 64))[lane] = make_uint2(*(uint32_t*)&lo, *(uint32_t*)&hi);
    }
}

// ---------------------------------------------------------------------------
// K4: hid = leaky(W1 @ h), fp16 (unchanged from round 13). grid (PQ/128, B).
// ---------------------------------------------------------------------------
__global__ void __launch_bounds__(256) k_gemm_w1()
{
    extern __shared__ uint32_t sm[];
    uint32_t* Ah = sm;                    // [128][68]
    uint32_t* Bs = sm + 128 * 68;         // [2][128][20]

    const int b = blockIdx.y;
    const int p0 = blockIdx.x * 128;
    const int tid = threadIdx.x;
    const uint32_t* A = g_hh + (size_t)(b * PQ + p0) * 64;

#pragma unroll
    for (int it = 0; it < 8; it++) {
        int id = tid + it * 256;
        int r = id >> 4, seg = (id & 15) * 4;
        cp16(&Ah[r * 68 + seg], A + (size_t)r * 64 + seg);
    }
    cp_commit();

    const int lane = tid & 31, wid = tid >> 5;
    const int gid = lane >> 2, tig = lane & 3;

#pragma unroll 1
    for (int nt4 = 0; nt4 < 4; nt4++) {
        const int co0 = nt4 * 128;
        float acc[4][4][4] = {};
        gemm_f16_Ares_pass(Ah, Bs, g_w1h + (size_t)co0 * 64, acc, tid);

        uint32_t* base = g_hidh + (size_t)(b * PQ + p0 + (wid & 1) * 64) * (HIDQ / 2)
                       + co0 / 2 + (wid >> 1) * 16;
#pragma unroll
        for (int mt = 0; mt < 4; mt++) {
            int r = mt * 16 + gid;
#pragma unroll
            for (int nt = 0; nt < 4; nt++) {
                int h2i = nt * 4 + tig;
                float v0 = acc[mt][nt][0], v1 = acc[mt][nt][1];
                float v2 = acc[mt][nt][2], v3 = acc[mt][nt][3];
                v0 = v0 > 0.f ? v0 : 0.2f * v0;
                v1 = v1 > 0.f ? v1 : 0.2f * v1;
                v2 = v2 > 0.f ? v2 : 0.2f * v2;
                v3 = v3 > 0.f ? v3 : 0.2f * v3;
                __half2 lo = __floats2half2_rn(v0, v1);
                __half2 hi = __floats2half2_rn(v2, v3);
                base[(size_t)r * (HIDQ / 2) + h2i]       = *(uint32_t*)&lo;
                base[(size_t)(r + 8) * (HIDQ / 2) + h2i] = *(uint32_t*)&hi;
            }
        }
    }
}

// ---------------------------------------------------------------------------
// K5: y = W2 @ hid, fp16 streaming (unchanged from round 13).
// ---------------------------------------------------------------------------
__global__ void __launch_bounds__(256) k_gemm_w2(float* __restrict__ out)
{
    __shared__ uint32_t As[2][128 * 20];
    __shared__ uint32_t Bs[2][128 * 20];

    const int b = blockIdx.z;
    const int p0 = blockIdx.x * 128;
    const int tid = threadIdx.x;
    const uint32_t* Ag = g_hidh + (size_t)(b * PQ + p0) * (HIDQ / 2);

    const int lane = tid & 31, wid = tid >> 5;
    const int gid = lane >> 2, tig = lane & 3;
    const int mbase = (wid & 1) * 64, nbase = (wid >> 1) * 32;
    const int r0 = tid >> 2, s0 = (tid & 3) * 4;
    const int r1 = r0 + 64;

    float acc[4][4][4] = {};

    cp16(&As[0][r0 * 20 + s0], Ag + (size_t)r0 * (HIDQ / 2) + s0);
    cp16(&As[0][r1 * 20 + s0], Ag + (size_t)r1 * (HIDQ / 2) + s0);
    cp16(&Bs[0][r0 * 20 + s0], g_w2h + (size_t)r0 * (HIDQ / 2) + s0);
    cp16(&Bs[0][r1 * 20 + s0], g_w2h + (size_t)r1 * (HIDQ / 2) + s0);
    cp_commit();

#pragma unroll 1
    for (int kc = 0; kc < 16; kc++) {
        const int st = kc & 1;
        cp_wait<0>();
        __syncthreads();
        if (kc + 1 < 16) {
            const int k0g = (kc + 1) * 16;
            cp16(&As[st ^ 1][r0 * 20 + s0], Ag + (size_t)r0 * (HIDQ / 2) + k0g + s0);
            cp16(&As[st ^ 1][r1 * 20 + s0], Ag + (size_t)r1 * (HIDQ / 2) + k0g + s0);
            cp16(&Bs[st ^ 1][r0 * 20 + s0], g_w2h + (size_t)r0 * (HIDQ / 2) + k0g + s0);
            cp16(&Bs[st ^ 1][r1 * 20 + s0], g_w2h + (size_t)r1 * (HIDQ / 2) + k0g + s0);
            cp_commit();
        }

#pragma unroll
        for (int ks = 0; ks < 2; ks++) {
            const int k0 = ks * 8;
            uint32_t af[4][4], bf[4][2];
#pragma unroll
            for (int mt = 0; mt < 4; mt++) {
                int m = mbase + mt * 16 + gid;
                af[mt][0] = As[st][m * 20 + k0 + tig];
                af[mt][1] = As[st][(m + 8) * 20 + k0 + tig];
                af[mt][2] = As[st][m * 20 + k0 + 4 + tig];
                af[mt][3] = As[st][(m + 8) * 20 + k0 + 4 + tig];
            }
#pragma unroll
            for (int nt = 0; nt < 4; nt++) {
                int n = nbase + nt * 8 + gid;
                bf[nt][0] = Bs[st][n * 20 + k0 + tig];
                bf[nt][1] = Bs[st][n * 20 + k0 + 4 + tig];
            }
#pragma unroll
            for (int mt = 0; mt < 4; mt++)
#pragma unroll
                for (int nt = 0; nt < 4; nt++)
                    mma_f16(acc[mt][nt], af[mt][0], af[mt][1], af[mt][2], af[mt][3],
                            bf[nt][0], bf[nt][1]);
        }
    }

    float* ob = out + (size_t)b * OUTC * PQ + (size_t)4 * PQ;
    int rbase = p0 + mbase;
#pragma unroll
    for (int mt = 0; mt < 4; mt++) {
        int r = rbase + mt * 16 + gid;
#pragma unroll
        for (int nt = 0; nt < 4; nt++) {
            int c = nbase + nt * 8 + tig * 2;
            ob[(size_t)c * PQ + r]           = acc[mt][nt][0];
            ob[(size_t)(c + 1) * PQ + r]     = acc[mt][nt][1];
            ob[(size_t)c * PQ + r + 8]       = acc[mt][nt][2];
            ob[(size_t)(c + 1) * PQ + r + 8] = acc[mt][nt][3];
        }
    }
}

// ---------------------------------------------------------------------------
extern "C" void kernel_launch(void* const* d_in, const int* in_sizes, int n_in,
                              void* d_out, int out_size)
{
    const float* x     = (const float*)d_in[0];
    const float* Wq    = (const float*)d_in[1];
    const float* Wk    = (const float*)d_in[2];
    const float* Wv    = (const float*)d_in[3];
    const float* W1    = (const float*)d_in[4];
    const float* W2    = (const float*)d_in[5];
    const float* gamma = (const float*)d_in[6];
    const float* beta  = (const float*)d_in[7];
    const float* mean  = (const float*)d_in[8];
    const float* var   = (const float*)d_in[9];
    float* out = (float*)d_out;

    static cudaStream_t s2;
    static cudaEvent_t evFork, evJoin;
    static int init_done = 0;
    if (!init_done) {
        cudaFuncSetAttribute(k_gemm_qkv, cudaFuncAttributeMaxDynamicSharedMemorySize, F16_ARES_SMEM);
        cudaFuncSetAttribute(k_gemm_w1,  cudaFuncAttributeMaxDynamicSharedMemorySize, F16_ARES_SMEM);
        cudaStreamCreateWithFlags(&s2, cudaStreamNonBlocking);
        cudaEventCreateWithFlags(&evFork, cudaEventDisableTiming);
        cudaEventCreateWithFlags(&evJoin, cudaEventDisableTiming);
        init_done = 1;
    }

    // Round-8 structure: single fork for topk, everything else serial full-grid.
    cudaEventRecord(evFork, 0);
    cudaStreamWaitEvent(s2, evFork, 0);
    k_topk<<<dim3(TQ, BQ, 8), 256, 0, s2>>>(x);
    cudaEventRecord(evJoin, s2);

    k_roundw<<<256, 256>>>(Wq, Wk, Wv, W1, W2);
    k_transpose<<<dim3(PQ / 32, CQ / 32, BQ), dim3(32, 8)>>>(x, out);
    k_gemm_qkv<<<dim3(PQ / 128, BQ), 256, F16_ARES_SMEM>>>();

    cudaStreamWaitEvent(0, evJoin, 0);
    k_attn<<<dim3((BQ * PQ) / 64, 1, 1), 256>>>(gamma, beta, mean, var);
    k_gemm_w1<<<dim3(PQ / 128, BQ), 256, F16_ARES_SMEM>>>();
    k_gemm_w2<<<dim3(PQ / 128, 1, BQ), 256>>>(out);
}